// round 7
// baseline (speedup 1.0000x reference)
#include <cuda_runtime.h>
#include <cuda_fp16.h>
#include <cstdint>
#include <math.h>

// Problem constants
#define BB     8
#define TLEN   2048
#define HIDD   1024
#define NHH    16
#define MDD    16
#define BT     (BB * TLEN)          // 16384 rows
#define N1     (NHH * MDD * MDD)    // 4096
#define K2D    (NHH * MDD * 2)      // 512

#define LO_SCALE    2048.0f
#define INV_LO      (1.0f / 2048.0f)

// ---------------------------------------------------------------------------
// Scratch (device globals — no allocation allowed)
// ---------------------------------------------------------------------------
__device__ float  g_m[(size_t)BT * N1];               // scan layout [s][t][256]
__device__ __half g_ah[(size_t)BT * HIDD];            // hs hi
__device__ __half g_al[(size_t)BT * HIDD];            // hs lo (*2048)
__device__ __half g_bh[(size_t)N1 * HIDD];            // W_mat^T hi  [n][k]
__device__ __half g_bl[(size_t)N1 * HIDD];            // W_mat^T lo  [n][k] (*2048)
__device__ __half g_xh[(size_t)BT * K2D];             // scan out hi
__device__ __half g_xl[(size_t)BT * K2D];             // scan out lo (*2048)
__device__ __half g_wh[(size_t)HIDD * K2D];           // W_out^T hi [n][k]
__device__ __half g_wl[(size_t)HIDD * K2D];           // W_out^T lo [n][k] (*2048)

// ---------------------------------------------------------------------------
// Helpers
// ---------------------------------------------------------------------------
__device__ __forceinline__ uint32_t smem_u32(const void* p) {
    uint32_t a;
    asm("{ .reg .u64 t; cvta.to.shared.u64 t, %1; cvt.u32.u64 %0, t; }" : "=r"(a) : "l"(p));
    return a;
}
#define CP_ASYNC16(dst, src) \
    asm volatile("cp.async.cg.shared.global [%0], [%1], 16;\n" :: "r"(dst), "l"(src) : "memory")
#define CP_COMMIT()  asm volatile("cp.async.commit_group;\n" ::: "memory")
#define CP_WAIT3()   asm volatile("cp.async.wait_group 3;\n" ::: "memory")

__device__ __forceinline__ void ldsm_x4(uint32_t& r0, uint32_t& r1, uint32_t& r2,
                                        uint32_t& r3, uint32_t addr) {
    asm volatile("ldmatrix.sync.aligned.m8n8.x4.shared.b16 {%0,%1,%2,%3}, [%4];"
                 : "=r"(r0), "=r"(r1), "=r"(r2), "=r"(r3) : "r"(addr));
}
__device__ __forceinline__ void mma_f16(float* c, const uint32_t* a, const uint32_t* b) {
    asm volatile(
        "mma.sync.aligned.m16n8k16.row.col.f32.f16.f16.f32 "
        "{%0,%1,%2,%3}, {%4,%5,%6,%7}, {%8,%9}, {%0,%1,%2,%3};"
        : "+f"(c[0]), "+f"(c[1]), "+f"(c[2]), "+f"(c[3])
        : "r"(a[0]), "r"(a[1]), "r"(a[2]), "r"(a[3]), "r"(b[0]), "r"(b[1]));
}
__device__ __forceinline__ uint32_t swz(uint32_t off) { return off ^ ((off >> 3) & 0x70); }

__device__ __forceinline__ void split_f16(float a, __half& h, __half& l) {
    h = __float2half_rn(a);
    l = __float2half_rn((a - __half2float(h)) * LO_SCALE);
}

// ---------------------------------------------------------------------------
// Conversion kernels
// ---------------------------------------------------------------------------
struct alignas(8) h4 { __half v[4]; };

__global__ __launch_bounds__(256)
void convA_kernel(const float* __restrict__ x, __half* __restrict__ hi,
                  __half* __restrict__ lo)
{
    const int i = blockIdx.x * blockDim.x + threadIdx.x;   // float4 index
    float4 v = ((const float4*)x)[i];
    h4 h, l;
    float a[4] = {v.x, v.y, v.z, v.w};
#pragma unroll
    for (int j = 0; j < 4; j++) split_f16(a[j], h.v[j], l.v[j]);
    ((h4*)hi)[i] = h;
    ((h4*)lo)[i] = l;
}

// Transpose W (KR x NC, row-major) -> [n][k] fp16 hi/lo
__global__ __launch_bounds__(1024)
void convW_kernel(const float* __restrict__ W, __half* __restrict__ wh,
                  __half* __restrict__ wl, int KR, int NC)
{
    __shared__ float tile[32][33];
    const int n_in = blockIdx.x * 32 + threadIdx.x;
    const int k_in = blockIdx.y * 32 + threadIdx.y;
    tile[threadIdx.y][threadIdx.x] = W[(size_t)k_in * NC + n_in];
    __syncthreads();
    const int n_out = blockIdx.x * 32 + threadIdx.y;
    const int k_out = blockIdx.y * 32 + threadIdx.x;
    const float v = tile[threadIdx.x][threadIdx.y];
    __half h, l;
    split_f16(v, h, l);
    const size_t o = (size_t)n_out * KR + k_out;
    wh[o] = h;
    wl[o] = l;
}

// ---------------------------------------------------------------------------
// HMMA GEMM, fp16 2-term split (3 products, dual accumulators):
//   D = (Ah*Bh) + (Ah*Bl + Al*Bh)/2048   [+ bias]
// CTA tile 128x128, 8 warps (2m x 4n), warp tile 64x32.
// 4-stage cp.async ring, K-chunk = 64 halfs (128B rows, SW128 swizzle).
// PERM: permuted store into scan layout (requires N-grid mapping of GEMM1).
// GELU: exact-erf gelu epilogue.
// ---------------------------------------------------------------------------
#define STAGE_BYTES 32768            // A 16KB + B 16KB
#define GEMM_SMEM   (1024 + 4 * STAGE_BYTES)

template <bool PERM, bool GELU, int KDIM, int NDIM>
__global__ __launch_bounds__(256)
void gemm_mma_kernel(const __half* __restrict__ Ah, const __half* __restrict__ Al,
                     const __half* __restrict__ Bh, const __half* __restrict__ Bl,
                     const float* __restrict__ bias, float* __restrict__ C)
{
    constexpr int CHUNKS = KDIM / 64;
    constexpr int NITER  = 3 * CHUNKS;

    extern __shared__ char smem[];
    const uint32_t tiles = (smem_u32(smem) + 1023u) & ~1023u;
    const int tid = threadIdx.x;
    const int lane = tid & 31, warp = tid >> 5;
    const int wm = warp & 1, wn = warp >> 1;     // 2 x 4 warp grid
    const int bx = blockIdx.x;                   // N tile
    const int by = blockIdx.y;                   // M tile

    const __half* Asrc[3] = {Ah, Ah, Al};
    const __half* Bsrc[3] = {Bh, Bl, Bh};

    // cp.async assignment: 256 threads, 16B each, 32 rows per pass
    const int lr = tid >> 3;           // 0..31
    const int lc = (tid & 7) * 16;     // byte col in 128B row

    auto issue_loads = [&](int iter) {
        const int pass = iter / CHUNKS, chunk = iter % CHUNKS, stage = iter & 3;
        const uint32_t a_s = tiles + stage * STAGE_BYTES;
        const uint32_t b_s = a_s + 16384;
        const __half* Ap = Asrc[pass] + (size_t)(by * 128) * KDIM + chunk * 64 + (lc >> 1);
        const __half* Bp = Bsrc[pass] + (size_t)(bx * 128) * KDIM + chunk * 64 + (lc >> 1);
#pragma unroll
        for (int it = 0; it < 4; it++) {
            const int row = it * 32 + lr;
            CP_ASYNC16(a_s + swz(row * 128 + lc), Ap + (size_t)row * KDIM);
        }
#pragma unroll
        for (int it = 0; it < 4; it++) {
            const int row = it * 32 + lr;
            CP_ASYNC16(b_s + swz(row * 128 + lc), Bp + (size_t)row * KDIM);
        }
    };

    float acc[2][4][4][4];      // [hi/lo][mt][nt][frag]
#pragma unroll
    for (int h = 0; h < 2; h++)
#pragma unroll
        for (int i = 0; i < 4; i++)
#pragma unroll
            for (int j = 0; j < 4; j++)
#pragma unroll
                for (int k = 0; k < 4; k++) acc[h][i][j][k] = 0.0f;

    const int lrow = lane & 15;
    const int lkof = (lane >> 4) * 16;

    for (int j = 0; j < 4; j++) { issue_loads(j); CP_COMMIT(); }

    for (int i = 0; i < NITER; i++) {
        CP_WAIT3();
        __syncthreads();
        const uint32_t a_s = tiles + (i & 3) * STAGE_BYTES;
        const uint32_t b_s = a_s + 16384;
        const int sel = (i >= CHUNKS) ? 1 : 0;   // pass 0 -> hi, passes 1,2 -> lo

#pragma unroll
        for (int ks = 0; ks < 4; ks++) {
            const int kb = ks * 32 + lkof;
            uint32_t a[4][4], b[4][2];
#pragma unroll
            for (int mt = 0; mt < 4; mt++) {
                const int row = wm * 64 + mt * 16 + lrow;
                ldsm_x4(a[mt][0], a[mt][1], a[mt][2], a[mt][3],
                        a_s + swz(row * 128 + kb));
            }
#pragma unroll
            for (int bt = 0; bt < 2; bt++) {
                const int row = wn * 32 + bt * 16 + lrow;
                uint32_t r0, r1, r2, r3;
                ldsm_x4(r0, r1, r2, r3, b_s + swz(row * 128 + kb));
                b[bt * 2 + 0][0] = r0; b[bt * 2 + 1][0] = r1;
                b[bt * 2 + 0][1] = r2; b[bt * 2 + 1][1] = r3;
            }
#pragma unroll
            for (int mt = 0; mt < 4; mt++)
#pragma unroll
                for (int nt = 0; nt < 4; nt++)
                    mma_f16(acc[sel][mt][nt], a[mt], b[nt]);
        }
        __syncthreads();
        if (i + 4 < NITER) issue_loads(i + 4);
        CP_COMMIT();
    }

    // ---- epilogue ----
    const int g = lane >> 2, t4 = lane & 3;
#pragma unroll
    for (int mt = 0; mt < 4; mt++) {
#pragma unroll
        for (int nt = 0; nt < 4; nt++) {
            const int rm = by * 128 + wm * 64 + mt * 16 + g;
            const int cg = bx * 128 + wn * 32 + nt * 8 + t4 * 2;
            const float b0 = __ldg(&bias[cg]);
            const float b1 = __ldg(&bias[cg + 1]);
            float v0 = acc[0][mt][nt][0] + acc[1][mt][nt][0] * INV_LO + b0;
            float v1 = acc[0][mt][nt][1] + acc[1][mt][nt][1] * INV_LO + b1;
            float v2 = acc[0][mt][nt][2] + acc[1][mt][nt][2] * INV_LO + b0;
            float v3 = acc[0][mt][nt][3] + acc[1][mt][nt][3] * INV_LO + b1;
            if (GELU) {
                v0 = 0.5f * v0 * (1.0f + erff(v0 * 0.70710678118654752f));
                v1 = 0.5f * v1 * (1.0f + erff(v1 * 0.70710678118654752f));
                v2 = 0.5f * v2 * (1.0f + erff(v2 * 0.70710678118654752f));
                v3 = 0.5f * v3 * (1.0f + erff(v3 * 0.70710678118654752f));
            }
            if (PERM) {
                const int nh = cg >> 8, ij = cg & 255;
                const int b_ = rm >> 11, t_ = rm & (TLEN - 1);
                float* o = C + (((size_t)(b_ * 16 + nh) * TLEN + t_) * 256 + ij);
                *(float2*)o = make_float2(v0, v1);
                *(float2*)(o + 8 * 256) = make_float2(v2, v3);
            } else {
                float* o = C + ((size_t)rm * NDIM + cg);
                *(float2*)o = make_float2(v0, v1);
                *(float2*)(o + (size_t)8 * NDIM) = make_float2(v2, v3);
            }
        }
    }
}

// ---------------------------------------------------------------------------
// In-place Frobenius normalization: one warp per 16x16 matrix.
// ---------------------------------------------------------------------------
__global__ __launch_bounds__(256)
void fro_norm_kernel(float* __restrict__ m)
{
    const size_t mat = (size_t)blockIdx.x * 8 + (threadIdx.x >> 5);
    const int lane = threadIdx.x & 31;
    float* p = m + mat * 256 + lane * 8;
    float4 a = *(float4*)p;
    float4 b = *(float4*)(p + 4);
    float ss = a.x * a.x + a.y * a.y + a.z * a.z + a.w * a.w
             + b.x * b.x + b.y * b.y + b.z * b.z + b.w * b.w;
    ss += __shfl_xor_sync(0xffffffffu, ss, 16);
    ss += __shfl_xor_sync(0xffffffffu, ss, 8);
    ss += __shfl_xor_sync(0xffffffffu, ss, 4);
    ss += __shfl_xor_sync(0xffffffffu, ss, 2);
    ss += __shfl_xor_sync(0xffffffffu, ss, 1);
    const float sc = 4.0f / (sqrtf(ss) + 1e-5f);
    a.x *= sc; a.y *= sc; a.z *= sc; a.w *= sc;
    b.x *= sc; b.y *= sc; b.z *= sc; b.w *= sc;
    *(float4*)p = a;
    *(float4*)(p + 4) = b;
}

// ---------------------------------------------------------------------------
// Sequential normalized-matvec scan. One warp per (sequence, direction).
// Emits x as fp16 hi/lo split (lo * 2048) for the HMMA GEMM2.
// ---------------------------------------------------------------------------
__global__ __launch_bounds__(64)
void scan_kernel(const float* __restrict__ mn, __half* __restrict__ xh,
                 __half* __restrict__ xl)
{
    const unsigned F = 0xffffffffu;
    const int warp = threadIdx.x >> 5;
    const int lane = threadIdx.x & 31;
    const int s = blockIdx.x;
    const int d = warp;
    const int b = s >> 4;
    const int nh = s & 15;

    const int laneoff = (lane & 15) * 16 + (lane >> 4) * 8;
    const float* base = mn + (size_t)s * (TLEN * 256) + laneoff;
    const int h8 = (lane >> 4) << 3;

    const int t0 = d ? (TLEN - 1) : 0;
    const int dt = d ? -1 : 1;

    float v = ((lane & 15) == 0) ? 1.0f : 0.0f;
    const size_t xoff = (size_t)b * TLEN * 512 + nh * 32 + d * 16 + (lane & 15);

    const float* p0 = base + (size_t)t0 * 256;
    float4 c0 = __ldg((const float4*)p0);
    float4 c1 = __ldg((const float4*)(p0 + 4));

#pragma unroll 1
    for (int step = 0; step < TLEN; ++step) {
        const int t = t0 + step * dt;
        int tn = t + dt;
        tn = tn < 0 ? 0 : (tn > TLEN - 1 ? TLEN - 1 : tn);
        const float* q = base + (size_t)tn * 256;
        float4 n0 = __ldg((const float4*)q);
        float4 n1 = __ldg((const float4*)(q + 4));

        const float vb0 = __shfl_sync(F, v, h8 + 0);
        const float vb1 = __shfl_sync(F, v, h8 + 1);
        const float vb2 = __shfl_sync(F, v, h8 + 2);
        const float vb3 = __shfl_sync(F, v, h8 + 3);
        const float vb4 = __shfl_sync(F, v, h8 + 4);
        const float vb5 = __shfl_sync(F, v, h8 + 5);
        const float vb6 = __shfl_sync(F, v, h8 + 6);
        const float vb7 = __shfl_sync(F, v, h8 + 7);

        float pA = c0.x * vb0;
        pA = fmaf(c0.y, vb1, pA);
        pA = fmaf(c0.z, vb2, pA);
        pA = fmaf(c0.w, vb3, pA);
        float pB = c1.x * vb4;
        pB = fmaf(c1.y, vb5, pB);
        pB = fmaf(c1.z, vb6, pB);
        pB = fmaf(c1.w, vb7, pB);
        float pp = pA + pB;

        const float nv = pp + __shfl_xor_sync(F, pp, 16);

        float ss = nv * nv;
        ss += __shfl_xor_sync(F, ss, 8);
        ss += __shfl_xor_sync(F, ss, 4);
        ss += __shfl_xor_sync(F, ss, 2);
        ss += __shfl_xor_sync(F, ss, 1);

        v = nv * (1.0f / (sqrtf(ss) + 1e-6f));

        if (lane < 16) {
            __half h, l;
            split_f16(v, h, l);
            xh[xoff + (size_t)t * 512] = h;
            xl[xoff + (size_t)t * 512] = l;
        }

        c0 = n0;
        c1 = n1;
    }
}

// ---------------------------------------------------------------------------
// Launch
// ---------------------------------------------------------------------------
extern "C" void kernel_launch(void* const* d_in, const int* in_sizes, int n_in,
                              void* d_out, int out_size)
{
    const float* hs = (const float*)d_in[0];
    const float* Wm = (const float*)d_in[1];
    const float* bm = (const float*)d_in[2];
    const float* Wo = (const float*)d_in[3];
    const float* bo = (const float*)d_in[4];
    float* out = (float*)d_out;

    float* pm;
    __half *pah, *pal, *pbh, *pbl, *pxh, *pxl, *pwh, *pwl;
    cudaGetSymbolAddress((void**)&pm, g_m);
    cudaGetSymbolAddress((void**)&pah, g_ah);
    cudaGetSymbolAddress((void**)&pal, g_al);
    cudaGetSymbolAddress((void**)&pbh, g_bh);
    cudaGetSymbolAddress((void**)&pbl, g_bl);
    cudaGetSymbolAddress((void**)&pxh, g_xh);
    cudaGetSymbolAddress((void**)&pxl, g_xl);
    cudaGetSymbolAddress((void**)&pwh, g_wh);
    cudaGetSymbolAddress((void**)&pwl, g_wl);

    // 0) fp16 splits
    convA_kernel<<<(BT * HIDD / 4) / 256, 256>>>(hs, pah, pal);
    convW_kernel<<<dim3(N1 / 32, HIDD / 32), dim3(32, 32)>>>(Wm, pbh, pbl, HIDD, N1);
    convW_kernel<<<dim3(HIDD / 32, K2D / 32), dim3(32, 32)>>>(Wo, pwh, pwl, K2D, HIDD);

    // 1) GEMM1 (HMMA fp16 split) -> scan layout (+bias)
    cudaFuncSetAttribute(gemm_mma_kernel<true, false, HIDD, N1>,
                         cudaFuncAttributeMaxDynamicSharedMemorySize, GEMM_SMEM);
    gemm_mma_kernel<true, false, HIDD, N1>
        <<<dim3(N1 / 128, BT / 128), 256, GEMM_SMEM>>>(pah, pal, pbh, pbl, bm, pm);

    // 2) In-place Frobenius normalization
    fro_norm_kernel<<<(BT * NHH) / 8, 256>>>(pm);

    // 3) Bidirectional normalized-matvec scan -> fp16 hi/lo
    scan_kernel<<<128, 64>>>(pm, pxh, pxl);

    // 4) GEMM2 (HMMA fp16 split): out = gelu(x @ W_out + b_out)
    cudaFuncSetAttribute(gemm_mma_kernel<false, true, K2D, HIDD>,
                         cudaFuncAttributeMaxDynamicSharedMemorySize, GEMM_SMEM);
    gemm_mma_kernel<false, true, K2D, HIDD>
        <<<dim3(HIDD / 128, BT / 128), 256, GEMM_SMEM>>>(pxh, pxl, pwh, pwl, bo, out);
}

// round 8
// speedup vs baseline: 1.7679x; 1.7679x over previous
#include <cuda_runtime.h>
#include <cuda_fp16.h>
#include <cstdint>
#include <math.h>

// Problem constants
#define BB     8
#define TLEN   2048
#define HIDD   1024
#define NHH    16
#define MDD    16
#define BT     (BB * TLEN)          // 16384 rows
#define N1     (NHH * MDD * MDD)    // 4096
#define K2D    (NHH * MDD * 2)      // 512

// ---------------------------------------------------------------------------
// Scratch (device globals — no allocation allowed)
// ---------------------------------------------------------------------------
__device__ float  g_m[(size_t)BT * N1];               // scan layout [s][t][256]
__device__ __half g_ah[(size_t)BT * HIDD];            // hs hi
__device__ __half g_al[(size_t)BT * HIDD];            // hs lo (unscaled)
__device__ __half g_bh[(size_t)N1 * HIDD];            // W_mat^T hi  [n][k]
__device__ __half g_bl[(size_t)N1 * HIDD];            // W_mat^T lo  [n][k]
__device__ __half g_xh[(size_t)BT * K2D];             // scan out hi
__device__ __half g_xl[(size_t)BT * K2D];             // scan out lo
__device__ __half g_wh[(size_t)HIDD * K2D];           // W_out^T hi [n][k]
__device__ __half g_wl[(size_t)HIDD * K2D];           // W_out^T lo [n][k]

// ---------------------------------------------------------------------------
// Helpers
// ---------------------------------------------------------------------------
__device__ __forceinline__ uint32_t smem_u32(const void* p) {
    uint32_t a;
    asm("{ .reg .u64 t; cvta.to.shared.u64 t, %1; cvt.u32.u64 %0, t; }" : "=r"(a) : "l"(p));
    return a;
}
#define CP_ASYNC16(dst, src) \
    asm volatile("cp.async.cg.shared.global [%0], [%1], 16;\n" :: "r"(dst), "l"(src) : "memory")
#define CP_COMMIT()  asm volatile("cp.async.commit_group;\n" ::: "memory")
#define CP_WAIT3()   asm volatile("cp.async.wait_group 3;\n" ::: "memory")

__device__ __forceinline__ void ldsm_x4(uint32_t& r0, uint32_t& r1, uint32_t& r2,
                                        uint32_t& r3, uint32_t addr) {
    asm volatile("ldmatrix.sync.aligned.m8n8.x4.shared.b16 {%0,%1,%2,%3}, [%4];"
                 : "=r"(r0), "=r"(r1), "=r"(r2), "=r"(r3) : "r"(addr));
}
__device__ __forceinline__ void mma_f16(float* c, const uint32_t* a, const uint32_t* b) {
    asm volatile(
        "mma.sync.aligned.m16n8k16.row.col.f32.f16.f16.f32 "
        "{%0,%1,%2,%3}, {%4,%5,%6,%7}, {%8,%9}, {%0,%1,%2,%3};"
        : "+f"(c[0]), "+f"(c[1]), "+f"(c[2]), "+f"(c[3])
        : "r"(a[0]), "r"(a[1]), "r"(a[2]), "r"(a[3]), "r"(b[0]), "r"(b[1]));
}
__device__ __forceinline__ uint32_t swz(uint32_t off) { return off ^ ((off >> 3) & 0x70); }

__device__ __forceinline__ void split_f16(float a, __half& h, __half& l) {
    h = __float2half_rn(a);
    l = __float2half_rn(a - __half2float(h));   // unscaled residual (may be subnormal)
}

// ---------------------------------------------------------------------------
// Conversion kernels
// ---------------------------------------------------------------------------
struct alignas(8) h4 { __half v[4]; };

__global__ __launch_bounds__(256)
void convA_kernel(const float* __restrict__ x, __half* __restrict__ hi,
                  __half* __restrict__ lo)
{
    const int i = blockIdx.x * blockDim.x + threadIdx.x;   // float4 index
    float4 v = ((const float4*)x)[i];
    h4 h, l;
    float a[4] = {v.x, v.y, v.z, v.w};
#pragma unroll
    for (int j = 0; j < 4; j++) split_f16(a[j], h.v[j], l.v[j]);
    ((h4*)hi)[i] = h;
    ((h4*)lo)[i] = l;
}

// Transpose W (KR x NC, row-major) -> [n][k] fp16 hi/lo
__global__ __launch_bounds__(1024)
void convW_kernel(const float* __restrict__ W, __half* __restrict__ wh,
                  __half* __restrict__ wl, int KR, int NC)
{
    __shared__ float tile[32][33];
    const int n_in = blockIdx.x * 32 + threadIdx.x;
    const int k_in = blockIdx.y * 32 + threadIdx.y;
    tile[threadIdx.y][threadIdx.x] = W[(size_t)k_in * NC + n_in];
    __syncthreads();
    const int n_out = blockIdx.x * 32 + threadIdx.y;
    const int k_out = blockIdx.y * 32 + threadIdx.x;
    const float v = tile[threadIdx.x][threadIdx.y];
    __half h, l;
    split_f16(v, h, l);
    const size_t o = (size_t)n_out * KR + k_out;
    wh[o] = h;
    wl[o] = l;
}

// ---------------------------------------------------------------------------
// HMMA GEMM, fp16 2-term split, SINGLE fp32 accumulator (lo terms unscaled):
//   D = Ah*Bl + Al*Bh + Ah*Bh   [+ bias]    (small terms accumulated first)
// CTA tile 128x128, 8 warps (2m x 4n), warp tile 64x32.
// 4-stage cp.async ring, K-chunk = 64 halfs (128B rows, SW128 swizzle).
// PERM: permuted store into scan layout. GELU: exact-erf gelu epilogue.
// ---------------------------------------------------------------------------
#define STAGE_BYTES 32768            // A 16KB + B 16KB
#define GEMM_SMEM   (1024 + 4 * STAGE_BYTES)

template <bool PERM, bool GELU, int KDIM, int NDIM>
__global__ __launch_bounds__(256)
void gemm_mma_kernel(const __half* __restrict__ Ah, const __half* __restrict__ Al,
                     const __half* __restrict__ Bh, const __half* __restrict__ Bl,
                     const float* __restrict__ bias, float* __restrict__ C)
{
    constexpr int CHUNKS = KDIM / 64;
    constexpr int NITER  = 3 * CHUNKS;

    extern __shared__ char smem[];
    const uint32_t tiles = (smem_u32(smem) + 1023u) & ~1023u;
    const int tid = threadIdx.x;
    const int lane = tid & 31, warp = tid >> 5;
    const int wm = warp & 1, wn = warp >> 1;     // 2 x 4 warp grid
    const int bx = blockIdx.x;                   // N tile
    const int by = blockIdx.y;                   // M tile

    // small terms first, dominant product last
    const __half* Asrc[3] = {Ah, Al, Ah};
    const __half* Bsrc[3] = {Bl, Bh, Bh};

    // cp.async assignment: 256 threads, 16B each, 32 rows per pass
    const int lr = tid >> 3;           // 0..31
    const int lc = (tid & 7) * 16;     // byte col in 128B row

    auto issue_loads = [&](int iter) {
        const int pass = iter / CHUNKS, chunk = iter % CHUNKS, stage = iter & 3;
        const uint32_t a_s = tiles + stage * STAGE_BYTES;
        const uint32_t b_s = a_s + 16384;
        const __half* Ap = Asrc[pass] + (size_t)(by * 128) * KDIM + chunk * 64 + (lc >> 1);
        const __half* Bp = Bsrc[pass] + (size_t)(bx * 128) * KDIM + chunk * 64 + (lc >> 1);
#pragma unroll
        for (int it = 0; it < 4; it++) {
            const int row = it * 32 + lr;
            CP_ASYNC16(a_s + swz(row * 128 + lc), Ap + (size_t)row * KDIM);
        }
#pragma unroll
        for (int it = 0; it < 4; it++) {
            const int row = it * 32 + lr;
            CP_ASYNC16(b_s + swz(row * 128 + lc), Bp + (size_t)row * KDIM);
        }
    };

    float acc[4][4][4];
#pragma unroll
    for (int i = 0; i < 4; i++)
#pragma unroll
        for (int j = 0; j < 4; j++)
#pragma unroll
            for (int k = 0; k < 4; k++) acc[i][j][k] = 0.0f;

    const int lrow = lane & 15;
    const int lkof = (lane >> 4) * 16;

    for (int j = 0; j < 4; j++) { issue_loads(j); CP_COMMIT(); }

    for (int i = 0; i < NITER; i++) {
        CP_WAIT3();
        __syncthreads();
        const uint32_t a_s = tiles + (i & 3) * STAGE_BYTES;
        const uint32_t b_s = a_s + 16384;

#pragma unroll
        for (int ks = 0; ks < 4; ks++) {
            const int kb = ks * 32 + lkof;
            uint32_t a[4][4], b[4][2];
#pragma unroll
            for (int mt = 0; mt < 4; mt++) {
                const int row = wm * 64 + mt * 16 + lrow;
                ldsm_x4(a[mt][0], a[mt][1], a[mt][2], a[mt][3],
                        a_s + swz(row * 128 + kb));
            }
#pragma unroll
            for (int bt = 0; bt < 2; bt++) {
                const int row = wn * 32 + bt * 16 + lrow;
                uint32_t r0, r1, r2, r3;
                ldsm_x4(r0, r1, r2, r3, b_s + swz(row * 128 + kb));
                b[bt * 2 + 0][0] = r0; b[bt * 2 + 1][0] = r1;
                b[bt * 2 + 0][1] = r2; b[bt * 2 + 1][1] = r3;
            }
#pragma unroll
            for (int mt = 0; mt < 4; mt++)
#pragma unroll
                for (int nt = 0; nt < 4; nt++)
                    mma_f16(acc[mt][nt], a[mt], b[nt]);
        }
        __syncthreads();
        if (i + 4 < NITER) issue_loads(i + 4);
        CP_COMMIT();
    }

    // ---- epilogue ----
    const int g = lane >> 2, t4 = lane & 3;
#pragma unroll
    for (int mt = 0; mt < 4; mt++) {
#pragma unroll
        for (int nt = 0; nt < 4; nt++) {
            const int rm = by * 128 + wm * 64 + mt * 16 + g;
            const int cg = bx * 128 + wn * 32 + nt * 8 + t4 * 2;
            const float b0 = __ldg(&bias[cg]);
            const float b1 = __ldg(&bias[cg + 1]);
            float v0 = acc[mt][nt][0] + b0;
            float v1 = acc[mt][nt][1] + b1;
            float v2 = acc[mt][nt][2] + b0;
            float v3 = acc[mt][nt][3] + b1;
            if (GELU) {
                v0 = 0.5f * v0 * (1.0f + erff(v0 * 0.70710678118654752f));
                v1 = 0.5f * v1 * (1.0f + erff(v1 * 0.70710678118654752f));
                v2 = 0.5f * v2 * (1.0f + erff(v2 * 0.70710678118654752f));
                v3 = 0.5f * v3 * (1.0f + erff(v3 * 0.70710678118654752f));
            }
            if (PERM) {
                const int nh = cg >> 8, ij = cg & 255;
                const int b_ = rm >> 11, t_ = rm & (TLEN - 1);
                float* o = C + (((size_t)(b_ * 16 + nh) * TLEN + t_) * 256 + ij);
                *(float2*)o = make_float2(v0, v1);
                *(float2*)(o + 8 * 256) = make_float2(v2, v3);
            } else {
                float* o = C + ((size_t)rm * NDIM + cg);
                *(float2*)o = make_float2(v0, v1);
                *(float2*)(o + (size_t)8 * NDIM) = make_float2(v2, v3);
            }
        }
    }
}

// ---------------------------------------------------------------------------
// In-place Frobenius normalization: one warp per 16x16 matrix.
// ---------------------------------------------------------------------------
__global__ __launch_bounds__(256)
void fro_norm_kernel(float* __restrict__ m)
{
    const size_t mat = (size_t)blockIdx.x * 8 + (threadIdx.x >> 5);
    const int lane = threadIdx.x & 31;
    float* p = m + mat * 256 + lane * 8;
    float4 a = *(float4*)p;
    float4 b = *(float4*)(p + 4);
    float ss = a.x * a.x + a.y * a.y + a.z * a.z + a.w * a.w
             + b.x * b.x + b.y * b.y + b.z * b.z + b.w * b.w;
    ss += __shfl_xor_sync(0xffffffffu, ss, 16);
    ss += __shfl_xor_sync(0xffffffffu, ss, 8);
    ss += __shfl_xor_sync(0xffffffffu, ss, 4);
    ss += __shfl_xor_sync(0xffffffffu, ss, 2);
    ss += __shfl_xor_sync(0xffffffffu, ss, 1);
    const float sc = 4.0f / (sqrtf(ss) + 1e-5f);
    a.x *= sc; a.y *= sc; a.z *= sc; a.w *= sc;
    b.x *= sc; b.y *= sc; b.z *= sc; b.w *= sc;
    *(float4*)p = a;
    *(float4*)(p + 4) = b;
}

// ---------------------------------------------------------------------------
// Sequential normalized-matvec scan. One warp per (sequence, direction).
// Emits x as fp16 hi/lo split for the HMMA GEMM2.
// ---------------------------------------------------------------------------
__global__ __launch_bounds__(64)
void scan_kernel(const float* __restrict__ mn, __half* __restrict__ xh,
                 __half* __restrict__ xl)
{
    const unsigned F = 0xffffffffu;
    const int warp = threadIdx.x >> 5;
    const int lane = threadIdx.x & 31;
    const int s = blockIdx.x;
    const int d = warp;
    const int b = s >> 4;
    const int nh = s & 15;

    const int laneoff = (lane & 15) * 16 + (lane >> 4) * 8;
    const float* base = mn + (size_t)s * (TLEN * 256) + laneoff;
    const int h8 = (lane >> 4) << 3;

    const int t0 = d ? (TLEN - 1) : 0;
    const int dt = d ? -1 : 1;

    float v = ((lane & 15) == 0) ? 1.0f : 0.0f;
    const size_t xoff = (size_t)b * TLEN * 512 + nh * 32 + d * 16 + (lane & 15);

    const float* p0 = base + (size_t)t0 * 256;
    float4 c0 = __ldg((const float4*)p0);
    float4 c1 = __ldg((const float4*)(p0 + 4));

#pragma unroll 1
    for (int step = 0; step < TLEN; ++step) {
        const int t = t0 + step * dt;
        int tn = t + dt;
        tn = tn < 0 ? 0 : (tn > TLEN - 1 ? TLEN - 1 : tn);
        const float* q = base + (size_t)tn * 256;
        float4 n0 = __ldg((const float4*)q);
        float4 n1 = __ldg((const float4*)(q + 4));

        const float vb0 = __shfl_sync(F, v, h8 + 0);
        const float vb1 = __shfl_sync(F, v, h8 + 1);
        const float vb2 = __shfl_sync(F, v, h8 + 2);
        const float vb3 = __shfl_sync(F, v, h8 + 3);
        const float vb4 = __shfl_sync(F, v, h8 + 4);
        const float vb5 = __shfl_sync(F, v, h8 + 5);
        const float vb6 = __shfl_sync(F, v, h8 + 6);
        const float vb7 = __shfl_sync(F, v, h8 + 7);

        float pA = c0.x * vb0;
        pA = fmaf(c0.y, vb1, pA);
        pA = fmaf(c0.z, vb2, pA);
        pA = fmaf(c0.w, vb3, pA);
        float pB = c1.x * vb4;
        pB = fmaf(c1.y, vb5, pB);
        pB = fmaf(c1.z, vb6, pB);
        pB = fmaf(c1.w, vb7, pB);
        float pp = pA + pB;

        const float nv = pp + __shfl_xor_sync(F, pp, 16);

        float ss = nv * nv;
        ss += __shfl_xor_sync(F, ss, 8);
        ss += __shfl_xor_sync(F, ss, 4);
        ss += __shfl_xor_sync(F, ss, 2);
        ss += __shfl_xor_sync(F, ss, 1);

        v = nv * (1.0f / (sqrtf(ss) + 1e-6f));

        if (lane < 16) {
            __half h, l;
            split_f16(v, h, l);
            xh[xoff + (size_t)t * 512] = h;
            xl[xoff + (size_t)t * 512] = l;
        }

        c0 = n0;
        c1 = n1;
    }
}

// ---------------------------------------------------------------------------
// Launch
// ---------------------------------------------------------------------------
extern "C" void kernel_launch(void* const* d_in, const int* in_sizes, int n_in,
                              void* d_out, int out_size)
{
    const float* hs = (const float*)d_in[0];
    const float* Wm = (const float*)d_in[1];
    const float* bm = (const float*)d_in[2];
    const float* Wo = (const float*)d_in[3];
    const float* bo = (const float*)d_in[4];
    float* out = (float*)d_out;

    float* pm;
    __half *pah, *pal, *pbh, *pbl, *pxh, *pxl, *pwh, *pwl;
    cudaGetSymbolAddress((void**)&pm, g_m);
    cudaGetSymbolAddress((void**)&pah, g_ah);
    cudaGetSymbolAddress((void**)&pal, g_al);
    cudaGetSymbolAddress((void**)&pbh, g_bh);
    cudaGetSymbolAddress((void**)&pbl, g_bl);
    cudaGetSymbolAddress((void**)&pxh, g_xh);
    cudaGetSymbolAddress((void**)&pxl, g_xl);
    cudaGetSymbolAddress((void**)&pwh, g_wh);
    cudaGetSymbolAddress((void**)&pwl, g_wl);

    // 0) fp16 splits
    convA_kernel<<<(BT * HIDD / 4) / 256, 256>>>(hs, pah, pal);
    convW_kernel<<<dim3(N1 / 32, HIDD / 32), dim3(32, 32)>>>(Wm, pbh, pbl, HIDD, N1);
    convW_kernel<<<dim3(HIDD / 32, K2D / 32), dim3(32, 32)>>>(Wo, pwh, pwl, K2D, HIDD);

    // 1) GEMM1 (HMMA fp16 split, single accumulator) -> scan layout (+bias)
    cudaFuncSetAttribute(gemm_mma_kernel<true, false, HIDD, N1>,
                         cudaFuncAttributeMaxDynamicSharedMemorySize, GEMM_SMEM);
    gemm_mma_kernel<true, false, HIDD, N1>
        <<<dim3(N1 / 128, BT / 128), 256, GEMM_SMEM>>>(pah, pal, pbh, pbl, bm, pm);

    // 2) In-place Frobenius normalization
    fro_norm_kernel<<<(BT * NHH) / 8, 256>>>(pm);

    // 3) Bidirectional normalized-matvec scan -> fp16 hi/lo
    scan_kernel<<<128, 64>>>(pm, pxh, pxl);

    // 4) GEMM2 (HMMA fp16 split): out = gelu(x @ W_out + b_out)
    cudaFuncSetAttribute(gemm_mma_kernel<false, true, K2D, HIDD>,
                         cudaFuncAttributeMaxDynamicSharedMemorySize, GEMM_SMEM);
    gemm_mma_kernel<false, true, K2D, HIDD>
        <<<dim3(HIDD / 128, BT / 128), 256, GEMM_SMEM>>>(pxh, pxl, pwh, pwl, bo, out);
}

// round 9
// speedup vs baseline: 1.8266x; 1.0332x over previous
#include <cuda_runtime.h>
#include <cuda_fp16.h>
#include <cstdint>
#include <math.h>

// Problem constants
#define BB     8
#define TLEN   2048
#define HIDD   1024
#define NHH    16
#define MDD    16
#define BT     (BB * TLEN)          // 16384 rows
#define N1     (NHH * MDD * MDD)    // 4096
#define K2D    (NHH * MDD * 2)      // 512

// ---------------------------------------------------------------------------
// Scratch (device globals — no allocation allowed)
// ---------------------------------------------------------------------------
__device__ float  g_m[(size_t)BT * N1];               // scan layout [s][t][256]
__device__ __half g_ah[(size_t)BT * HIDD];            // hs hi
__device__ __half g_al[(size_t)BT * HIDD];            // hs lo (unscaled)
__device__ __half g_bh[(size_t)N1 * HIDD];            // W_mat^T hi  [n][k]
__device__ __half g_bl[(size_t)N1 * HIDD];            // W_mat^T lo  [n][k]
__device__ __half g_xh[(size_t)BT * K2D];             // scan out hi
__device__ __half g_xl[(size_t)BT * K2D];             // scan out lo
__device__ __half g_wh[(size_t)HIDD * K2D];           // W_out^T hi [n][k]
__device__ __half g_wl[(size_t)HIDD * K2D];           // W_out^T lo [n][k]

// ---------------------------------------------------------------------------
// Helpers
// ---------------------------------------------------------------------------
__device__ __forceinline__ uint32_t smem_u32(const void* p) {
    uint32_t a;
    asm("{ .reg .u64 t; cvta.to.shared.u64 t, %1; cvt.u32.u64 %0, t; }" : "=r"(a) : "l"(p));
    return a;
}
#define CP_ASYNC16(dst, src) \
    asm volatile("cp.async.cg.shared.global [%0], [%1], 16;\n" :: "r"(dst), "l"(src) : "memory")
#define CP_COMMIT()  asm volatile("cp.async.commit_group;\n" ::: "memory")
#define CP_WAIT2()   asm volatile("cp.async.wait_group 2;\n" ::: "memory")

__device__ __forceinline__ void ldsm_x4(uint32_t& r0, uint32_t& r1, uint32_t& r2,
                                        uint32_t& r3, uint32_t addr) {
    asm volatile("ldmatrix.sync.aligned.m8n8.x4.shared.b16 {%0,%1,%2,%3}, [%4];"
                 : "=r"(r0), "=r"(r1), "=r"(r2), "=r"(r3) : "r"(addr));
}
__device__ __forceinline__ void mma_f16(float* c, const uint32_t* a, const uint32_t* b) {
    asm volatile(
        "mma.sync.aligned.m16n8k16.row.col.f32.f16.f16.f32 "
        "{%0,%1,%2,%3}, {%4,%5,%6,%7}, {%8,%9}, {%0,%1,%2,%3};"
        : "+f"(c[0]), "+f"(c[1]), "+f"(c[2]), "+f"(c[3])
        : "r"(a[0]), "r"(a[1]), "r"(a[2]), "r"(a[3]), "r"(b[0]), "r"(b[1]));
}
__device__ __forceinline__ uint32_t swz(uint32_t off) { return off ^ ((off >> 3) & 0x70); }

__device__ __forceinline__ void split_f16(float a, __half& h, __half& l) {
    h = __float2half_rn(a);
    l = __float2half_rn(a - __half2float(h));   // unscaled residual (may be subnormal)
}

// ---------------------------------------------------------------------------
// Conversion kernels
// ---------------------------------------------------------------------------
struct alignas(8) h4 { __half v[4]; };

__global__ __launch_bounds__(256)
void convA_kernel(const float* __restrict__ x, __half* __restrict__ hi,
                  __half* __restrict__ lo)
{
    const int i = blockIdx.x * blockDim.x + threadIdx.x;   // float4 index
    float4 v = ((const float4*)x)[i];
    h4 h, l;
    float a[4] = {v.x, v.y, v.z, v.w};
#pragma unroll
    for (int j = 0; j < 4; j++) split_f16(a[j], h.v[j], l.v[j]);
    ((h4*)hi)[i] = h;
    ((h4*)lo)[i] = l;
}

// Transpose W (KR x NC, row-major) -> [n][k] fp16 hi/lo
__global__ __launch_bounds__(1024)
void convW_kernel(const float* __restrict__ W, __half* __restrict__ wh,
                  __half* __restrict__ wl, int KR, int NC)
{
    __shared__ float tile[32][33];
    const int n_in = blockIdx.x * 32 + threadIdx.x;
    const int k_in = blockIdx.y * 32 + threadIdx.y;
    tile[threadIdx.y][threadIdx.x] = W[(size_t)k_in * NC + n_in];
    __syncthreads();
    const int n_out = blockIdx.x * 32 + threadIdx.y;
    const int k_out = blockIdx.y * 32 + threadIdx.x;
    const float v = tile[threadIdx.x][threadIdx.y];
    __half h, l;
    split_f16(v, h, l);
    const size_t o = (size_t)n_out * KR + k_out;
    wh[o] = h;
    wl[o] = l;
}

// ---------------------------------------------------------------------------
// HMMA GEMM, fp16 2-term split, single fp32 accumulator:
//   D = Ah*Bl + Al*Bh + Ah*Bh   [+ bias]
// CTA tile 128x128, 8 warps (2m x 4n), warp tile 64x32.
// 3-stage cp.async ring (97KB smem -> 2 CTAs/SM), K-chunk = 64 halfs.
// PERM: permuted store into scan layout. GELU: exact-erf gelu epilogue.
// ---------------------------------------------------------------------------
#define STAGE_BYTES 32768            // A 16KB + B 16KB
#define GEMM_SMEM   (1024 + 3 * STAGE_BYTES)

template <bool PERM, bool GELU, int KDIM, int NDIM>
__global__ __launch_bounds__(256, 2)
void gemm_mma_kernel(const __half* __restrict__ Ah, const __half* __restrict__ Al,
                     const __half* __restrict__ Bh, const __half* __restrict__ Bl,
                     const float* __restrict__ bias, float* __restrict__ C)
{
    constexpr int CHUNKS = KDIM / 64;
    constexpr int NITER  = 3 * CHUNKS;

    extern __shared__ char smem[];
    const uint32_t tiles = (smem_u32(smem) + 1023u) & ~1023u;
    const int tid = threadIdx.x;
    const int lane = tid & 31, warp = tid >> 5;
    const int wm = warp & 1, wn = warp >> 1;     // 2 x 4 warp grid
    const int bx = blockIdx.x;                   // N tile
    const int by = blockIdx.y;                   // M tile

    // small terms first, dominant product last
    const __half* Asrc[3] = {Ah, Al, Ah};
    const __half* Bsrc[3] = {Bl, Bh, Bh};

    // cp.async assignment: 256 threads, 16B each, 32 rows per pass
    const int lr = tid >> 3;           // 0..31
    const int lc = (tid & 7) * 16;     // byte col in 128B row

    auto issue_loads = [&](int iter) {
        const int pass = iter / CHUNKS, chunk = iter % CHUNKS, stage = iter % 3;
        const uint32_t a_s = tiles + stage * STAGE_BYTES;
        const uint32_t b_s = a_s + 16384;
        const __half* Ap = Asrc[pass] + (size_t)(by * 128) * KDIM + chunk * 64 + (lc >> 1);
        const __half* Bp = Bsrc[pass] + (size_t)(bx * 128) * KDIM + chunk * 64 + (lc >> 1);
#pragma unroll
        for (int it = 0; it < 4; it++) {
            const int row = it * 32 + lr;
            CP_ASYNC16(a_s + swz(row * 128 + lc), Ap + (size_t)row * KDIM);
        }
#pragma unroll
        for (int it = 0; it < 4; it++) {
            const int row = it * 32 + lr;
            CP_ASYNC16(b_s + swz(row * 128 + lc), Bp + (size_t)row * KDIM);
        }
    };

    float acc[4][4][4];
#pragma unroll
    for (int i = 0; i < 4; i++)
#pragma unroll
        for (int j = 0; j < 4; j++)
#pragma unroll
            for (int k = 0; k < 4; k++) acc[i][j][k] = 0.0f;

    const int lrow = lane & 15;
    const int lkof = (lane >> 4) * 16;

    for (int j = 0; j < 3; j++) { issue_loads(j); CP_COMMIT(); }

    for (int i = 0; i < NITER; i++) {
        CP_WAIT2();
        __syncthreads();
        const uint32_t a_s = tiles + (i % 3) * STAGE_BYTES;
        const uint32_t b_s = a_s + 16384;

#pragma unroll
        for (int ks = 0; ks < 4; ks++) {
            const int kb = ks * 32 + lkof;
            uint32_t a[4][4], b[4][2];
#pragma unroll
            for (int mt = 0; mt < 4; mt++) {
                const int row = wm * 64 + mt * 16 + lrow;
                ldsm_x4(a[mt][0], a[mt][1], a[mt][2], a[mt][3],
                        a_s + swz(row * 128 + kb));
            }
#pragma unroll
            for (int bt = 0; bt < 2; bt++) {
                const int row = wn * 32 + bt * 16 + lrow;
                uint32_t r0, r1, r2, r3;
                ldsm_x4(r0, r1, r2, r3, b_s + swz(row * 128 + kb));
                b[bt * 2 + 0][0] = r0; b[bt * 2 + 1][0] = r1;
                b[bt * 2 + 0][1] = r2; b[bt * 2 + 1][1] = r3;
            }
#pragma unroll
            for (int mt = 0; mt < 4; mt++)
#pragma unroll
                for (int nt = 0; nt < 4; nt++)
                    mma_f16(acc[mt][nt], a[mt], b[nt]);
        }
        __syncthreads();
        if (i + 3 < NITER) issue_loads(i + 3);
        CP_COMMIT();
    }

    // ---- epilogue ----
    const int g = lane >> 2, t4 = lane & 3;
#pragma unroll
    for (int mt = 0; mt < 4; mt++) {
#pragma unroll
        for (int nt = 0; nt < 4; nt++) {
            const int rm = by * 128 + wm * 64 + mt * 16 + g;
            const int cg = bx * 128 + wn * 32 + nt * 8 + t4 * 2;
            const float b0 = __ldg(&bias[cg]);
            const float b1 = __ldg(&bias[cg + 1]);
            float v0 = acc[mt][nt][0] + b0;
            float v1 = acc[mt][nt][1] + b1;
            float v2 = acc[mt][nt][2] + b0;
            float v3 = acc[mt][nt][3] + b1;
            if (GELU) {
                v0 = 0.5f * v0 * (1.0f + erff(v0 * 0.70710678118654752f));
                v1 = 0.5f * v1 * (1.0f + erff(v1 * 0.70710678118654752f));
                v2 = 0.5f * v2 * (1.0f + erff(v2 * 0.70710678118654752f));
                v3 = 0.5f * v3 * (1.0f + erff(v3 * 0.70710678118654752f));
            }
            if (PERM) {
                const int nh = cg >> 8, ij = cg & 255;
                const int b_ = rm >> 11, t_ = rm & (TLEN - 1);
                float* o = C + (((size_t)(b_ * 16 + nh) * TLEN + t_) * 256 + ij);
                *(float2*)o = make_float2(v0, v1);
                *(float2*)(o + 8 * 256) = make_float2(v2, v3);
            } else {
                float* o = C + ((size_t)rm * NDIM + cg);
                *(float2*)o = make_float2(v0, v1);
                *(float2*)(o + (size_t)8 * NDIM) = make_float2(v2, v3);
            }
        }
    }
}

// ---------------------------------------------------------------------------
// In-place Frobenius normalization: one warp per 16x16 matrix.
// ---------------------------------------------------------------------------
__global__ __launch_bounds__(256)
void fro_norm_kernel(float* __restrict__ m)
{
    const size_t mat = (size_t)blockIdx.x * 8 + (threadIdx.x >> 5);
    const int lane = threadIdx.x & 31;
    float* p = m + mat * 256 + lane * 8;
    float4 a = *(float4*)p;
    float4 b = *(float4*)(p + 4);
    float ss = a.x * a.x + a.y * a.y + a.z * a.z + a.w * a.w
             + b.x * b.x + b.y * b.y + b.z * b.z + b.w * b.w;
    ss += __shfl_xor_sync(0xffffffffu, ss, 16);
    ss += __shfl_xor_sync(0xffffffffu, ss, 8);
    ss += __shfl_xor_sync(0xffffffffu, ss, 4);
    ss += __shfl_xor_sync(0xffffffffu, ss, 2);
    ss += __shfl_xor_sync(0xffffffffu, ss, 1);
    const float sc = 4.0f / (sqrtf(ss) + 1e-5f);
    a.x *= sc; a.y *= sc; a.z *= sc; a.w *= sc;
    b.x *= sc; b.y *= sc; b.z *= sc; b.w *= sc;
    *(float4*)p = a;
    *(float4*)(p + 4) = b;
}

// ---------------------------------------------------------------------------
// Sequential scan, deferred normalization.
// u_{t+1} = M_t u_t  (unnormalized); output w_t = nv/(sqrt(ss)+eps) is off the
// critical path. u is rescaled to w every 4th step (statically unrolled, so
// the rescale select never puts sqrt/div on the recurrence path).
// Positive scaling commutes through the normalized recurrence, so this is
// mathematically identical up to eps weighting (~1e-6 relative).
// ---------------------------------------------------------------------------
__global__ __launch_bounds__(64)
void scan_kernel(const float* __restrict__ mn, __half* __restrict__ xh,
                 __half* __restrict__ xl)
{
    const unsigned F = 0xffffffffu;
    const int warp = threadIdx.x >> 5;
    const int lane = threadIdx.x & 31;
    const int s = blockIdx.x;
    const int d = warp;
    const int b = s >> 4;
    const int nh = s & 15;

    const int laneoff = (lane & 15) * 16 + (lane >> 4) * 8;
    const float* base = mn + (size_t)s * (TLEN * 256) + laneoff;
    const int h8 = (lane >> 4) << 3;

    const int t0 = d ? (TLEN - 1) : 0;
    const int dt = d ? -1 : 1;

    float u = ((lane & 15) == 0) ? 1.0f : 0.0f;
    const size_t xoff = (size_t)b * TLEN * 512 + nh * 32 + d * 16 + (lane & 15);

    const float* p0 = base + (size_t)t0 * 256;
    float4 c0 = __ldg((const float4*)p0);
    float4 c1 = __ldg((const float4*)(p0 + 4));

#pragma unroll 1
    for (int blk = 0; blk < TLEN / 4; ++blk) {
#pragma unroll
        for (int sub = 0; sub < 4; ++sub) {
            const int step = blk * 4 + sub;
            const int t = t0 + step * dt;
            int tn = t + dt;
            tn = tn < 0 ? 0 : (tn > TLEN - 1 ? TLEN - 1 : tn);
            const float* q = base + (size_t)tn * 256;
            float4 n0 = __ldg((const float4*)q);
            float4 n1 = __ldg((const float4*)(q + 4));

            const float vb0 = __shfl_sync(F, u, h8 + 0);
            const float vb1 = __shfl_sync(F, u, h8 + 1);
            const float vb2 = __shfl_sync(F, u, h8 + 2);
            const float vb3 = __shfl_sync(F, u, h8 + 3);
            const float vb4 = __shfl_sync(F, u, h8 + 4);
            const float vb5 = __shfl_sync(F, u, h8 + 5);
            const float vb6 = __shfl_sync(F, u, h8 + 6);
            const float vb7 = __shfl_sync(F, u, h8 + 7);

            float pA = c0.x * vb0;
            pA = fmaf(c0.y, vb1, pA);
            pA = fmaf(c0.z, vb2, pA);
            pA = fmaf(c0.w, vb3, pA);
            float pB = c1.x * vb4;
            pB = fmaf(c1.y, vb5, pB);
            pB = fmaf(c1.z, vb6, pB);
            pB = fmaf(c1.w, vb7, pB);
            const float pp = pA + pB;

            const float nv = pp + __shfl_xor_sync(F, pp, 16);

            // off-critical-path: norm + normalized output
            float ss = nv * nv;
            ss += __shfl_xor_sync(F, ss, 8);
            ss += __shfl_xor_sync(F, ss, 4);
            ss += __shfl_xor_sync(F, ss, 2);
            ss += __shfl_xor_sync(F, ss, 1);
            const float w = nv / (sqrtf(ss) + 1e-6f);

            if (lane < 16) {
                __half h, l;
                split_f16(w, h, l);
                xh[xoff + (size_t)t * 512] = h;
                xl[xoff + (size_t)t * 512] = l;
            }

            u = (sub == 3) ? w : nv;   // static select: no dependency on w
                                       // except on the rescale step
            c0 = n0;
            c1 = n1;
        }
    }
}

// ---------------------------------------------------------------------------
// Launch
// ---------------------------------------------------------------------------
extern "C" void kernel_launch(void* const* d_in, const int* in_sizes, int n_in,
                              void* d_out, int out_size)
{
    const float* hs = (const float*)d_in[0];
    const float* Wm = (const float*)d_in[1];
    const float* bm = (const float*)d_in[2];
    const float* Wo = (const float*)d_in[3];
    const float* bo = (const float*)d_in[4];
    float* out = (float*)d_out;

    float* pm;
    __half *pah, *pal, *pbh, *pbl, *pxh, *pxl, *pwh, *pwl;
    cudaGetSymbolAddress((void**)&pm, g_m);
    cudaGetSymbolAddress((void**)&pah, g_ah);
    cudaGetSymbolAddress((void**)&pal, g_al);
    cudaGetSymbolAddress((void**)&pbh, g_bh);
    cudaGetSymbolAddress((void**)&pbl, g_bl);
    cudaGetSymbolAddress((void**)&pxh, g_xh);
    cudaGetSymbolAddress((void**)&pxl, g_xl);
    cudaGetSymbolAddress((void**)&pwh, g_wh);
    cudaGetSymbolAddress((void**)&pwl, g_wl);

    // 0) fp16 splits
    convA_kernel<<<(BT * HIDD / 4) / 256, 256>>>(hs, pah, pal);
    convW_kernel<<<dim3(N1 / 32, HIDD / 32), dim3(32, 32)>>>(Wm, pbh, pbl, HIDD, N1);
    convW_kernel<<<dim3(HIDD / 32, K2D / 32), dim3(32, 32)>>>(Wo, pwh, pwl, K2D, HIDD);

    // 1) GEMM1 (HMMA fp16 split) -> scan layout (+bias)
    cudaFuncSetAttribute(gemm_mma_kernel<true, false, HIDD, N1>,
                         cudaFuncAttributeMaxDynamicSharedMemorySize, GEMM_SMEM);
    gemm_mma_kernel<true, false, HIDD, N1>
        <<<dim3(N1 / 128, BT / 128), 256, GEMM_SMEM>>>(pah, pal, pbh, pbl, bm, pm);

    // 2) In-place Frobenius normalization
    fro_norm_kernel<<<(BT * NHH) / 8, 256>>>(pm);

    // 3) Bidirectional scan (deferred normalization) -> fp16 hi/lo
    scan_kernel<<<128, 64>>>(pm, pxh, pxl);

    // 4) GEMM2 (HMMA fp16 split): out = gelu(x @ W_out + b_out)
    cudaFuncSetAttribute(gemm_mma_kernel<false, true, K2D, HIDD>,
                         cudaFuncAttributeMaxDynamicSharedMemorySize, GEMM_SMEM);
    gemm_mma_kernel<false, true, K2D, HIDD>
        <<<dim3(HIDD / 128, BT / 128), 256, GEMM_SMEM>>>(pxh, pxl, pwh, pwl, bo, out);
}

// round 10
// speedup vs baseline: 2.4167x; 1.3230x over previous
#include <cuda_runtime.h>
#include <cuda_fp16.h>
#include <cstdint>
#include <math.h>

// Problem constants
#define BB     8
#define TLEN   2048
#define HIDD   1024
#define NHH    16
#define MDD    16
#define BT     (BB * TLEN)          // 16384 rows
#define N1     (NHH * MDD * MDD)    // 4096
#define K2D    (NHH * MDD * 2)      // 512

// ---------------------------------------------------------------------------
// Scratch (device globals — no allocation allowed)
// ---------------------------------------------------------------------------
__device__ float  g_m[(size_t)BT * N1];               // scan layout [s][t][256]
__device__ __half g_ah[(size_t)BT * HIDD];            // hs hi
__device__ __half g_al[(size_t)BT * HIDD];            // hs lo (unscaled)
__device__ __half g_bh[(size_t)N1 * HIDD];            // W_mat^T hi  [n][k]
__device__ __half g_bl[(size_t)N1 * HIDD];            // W_mat^T lo  [n][k]
__device__ __half g_xh[(size_t)BT * K2D];             // scan out hi
__device__ __half g_xl[(size_t)BT * K2D];             // scan out lo
__device__ __half g_wh[(size_t)HIDD * K2D];           // W_out^T hi [n][k]
__device__ __half g_wl[(size_t)HIDD * K2D];           // W_out^T lo [n][k]

// ---------------------------------------------------------------------------
// Helpers
// ---------------------------------------------------------------------------
__device__ __forceinline__ uint32_t smem_u32(const void* p) {
    uint32_t a;
    asm("{ .reg .u64 t; cvta.to.shared.u64 t, %1; cvt.u32.u64 %0, t; }" : "=r"(a) : "l"(p));
    return a;
}
#define CP_ASYNC16(dst, src) \
    asm volatile("cp.async.cg.shared.global [%0], [%1], 16;\n" :: "r"(dst), "l"(src) : "memory")
#define CP_COMMIT()  asm volatile("cp.async.commit_group;\n" ::: "memory")
#define CP_WAIT2()   asm volatile("cp.async.wait_group 2;\n" ::: "memory")

__device__ __forceinline__ void ldsm_x4(uint32_t& r0, uint32_t& r1, uint32_t& r2,
                                        uint32_t& r3, uint32_t addr) {
    asm volatile("ldmatrix.sync.aligned.m8n8.x4.shared.b16 {%0,%1,%2,%3}, [%4];"
                 : "=r"(r0), "=r"(r1), "=r"(r2), "=r"(r3) : "r"(addr));
}
__device__ __forceinline__ void mma_f16(float* c, const uint32_t* a, const uint32_t* b) {
    asm volatile(
        "mma.sync.aligned.m16n8k16.row.col.f32.f16.f16.f32 "
        "{%0,%1,%2,%3}, {%4,%5,%6,%7}, {%8,%9}, {%0,%1,%2,%3};"
        : "+f"(c[0]), "+f"(c[1]), "+f"(c[2]), "+f"(c[3])
        : "r"(a[0]), "r"(a[1]), "r"(a[2]), "r"(a[3]), "r"(b[0]), "r"(b[1]));
}
__device__ __forceinline__ uint32_t swz(uint32_t off) { return off ^ ((off >> 3) & 0x70); }

__device__ __forceinline__ void split_f16(float a, __half& h, __half& l) {
    h = __float2half_rn(a);
    l = __float2half_rn(a - __half2float(h));   // unscaled residual (may be subnormal)
}

// ---------------------------------------------------------------------------
// Conversion kernels
// ---------------------------------------------------------------------------
struct alignas(8) h4 { __half v[4]; };

__global__ __launch_bounds__(256)
void convA_kernel(const float* __restrict__ x, __half* __restrict__ hi,
                  __half* __restrict__ lo)
{
    const int i = blockIdx.x * blockDim.x + threadIdx.x;   // float4 index
    float4 v = ((const float4*)x)[i];
    h4 h, l;
    float a[4] = {v.x, v.y, v.z, v.w};
#pragma unroll
    for (int j = 0; j < 4; j++) split_f16(a[j], h.v[j], l.v[j]);
    ((h4*)hi)[i] = h;
    ((h4*)lo)[i] = l;
}

// Transpose W (KR x NC, row-major) -> [n][k] fp16 hi/lo
__global__ __launch_bounds__(1024)
void convW_kernel(const float* __restrict__ W, __half* __restrict__ wh,
                  __half* __restrict__ wl, int KR, int NC)
{
    __shared__ float tile[32][33];
    const int n_in = blockIdx.x * 32 + threadIdx.x;
    const int k_in = blockIdx.y * 32 + threadIdx.y;
    tile[threadIdx.y][threadIdx.x] = W[(size_t)k_in * NC + n_in];
    __syncthreads();
    const int n_out = blockIdx.x * 32 + threadIdx.y;
    const int k_out = blockIdx.y * 32 + threadIdx.x;
    const float v = tile[threadIdx.x][threadIdx.y];
    __half h, l;
    split_f16(v, h, l);
    const size_t o = (size_t)n_out * KR + k_out;
    wh[o] = h;
    wl[o] = l;
}

// ---------------------------------------------------------------------------
// HMMA GEMM, fp16 2-term split, single fp32 accumulator:
//   D = Ah*Bl + Al*Bh + Ah*Bh   [+ bias]
// CTA tile 128x128, 8 warps (2m x 4n), warp tile 64x32.
// 3-stage cp.async ring (97KB smem -> 2 CTAs/SM), K-chunk = 64 halfs.
// ---------------------------------------------------------------------------
#define STAGE_BYTES 32768            // A 16KB + B 16KB
#define GEMM_SMEM   (1024 + 3 * STAGE_BYTES)

template <bool PERM, bool GELU, int KDIM, int NDIM>
__global__ __launch_bounds__(256, 2)
void gemm_mma_kernel(const __half* __restrict__ Ah, const __half* __restrict__ Al,
                     const __half* __restrict__ Bh, const __half* __restrict__ Bl,
                     const float* __restrict__ bias, float* __restrict__ C)
{
    constexpr int CHUNKS = KDIM / 64;
    constexpr int NITER  = 3 * CHUNKS;

    extern __shared__ char smem[];
    const uint32_t tiles = (smem_u32(smem) + 1023u) & ~1023u;
    const int tid = threadIdx.x;
    const int lane = tid & 31, warp = tid >> 5;
    const int wm = warp & 1, wn = warp >> 1;     // 2 x 4 warp grid
    const int bx = blockIdx.x;                   // N tile
    const int by = blockIdx.y;                   // M tile

    // small terms first, dominant product last
    const __half* Asrc[3] = {Ah, Al, Ah};
    const __half* Bsrc[3] = {Bl, Bh, Bh};

    const int lr = tid >> 3;           // 0..31
    const int lc = (tid & 7) * 16;     // byte col in 128B row

    auto issue_loads = [&](int iter) {
        const int pass = iter / CHUNKS, chunk = iter % CHUNKS, stage = iter % 3;
        const uint32_t a_s = tiles + stage * STAGE_BYTES;
        const uint32_t b_s = a_s + 16384;
        const __half* Ap = Asrc[pass] + (size_t)(by * 128) * KDIM + chunk * 64 + (lc >> 1);
        const __half* Bp = Bsrc[pass] + (size_t)(bx * 128) * KDIM + chunk * 64 + (lc >> 1);
#pragma unroll
        for (int it = 0; it < 4; it++) {
            const int row = it * 32 + lr;
            CP_ASYNC16(a_s + swz(row * 128 + lc), Ap + (size_t)row * KDIM);
        }
#pragma unroll
        for (int it = 0; it < 4; it++) {
            const int row = it * 32 + lr;
            CP_ASYNC16(b_s + swz(row * 128 + lc), Bp + (size_t)row * KDIM);
        }
    };

    float acc[4][4][4];
#pragma unroll
    for (int i = 0; i < 4; i++)
#pragma unroll
        for (int j = 0; j < 4; j++)
#pragma unroll
            for (int k = 0; k < 4; k++) acc[i][j][k] = 0.0f;

    const int lrow = lane & 15;
    const int lkof = (lane >> 4) * 16;

    for (int j = 0; j < 3; j++) { issue_loads(j); CP_COMMIT(); }

    for (int i = 0; i < NITER; i++) {
        CP_WAIT2();
        __syncthreads();
        const uint32_t a_s = tiles + (i % 3) * STAGE_BYTES;
        const uint32_t b_s = a_s + 16384;

#pragma unroll
        for (int ks = 0; ks < 4; ks++) {
            const int kb = ks * 32 + lkof;
            uint32_t a[4][4], b[4][2];
#pragma unroll
            for (int mt = 0; mt < 4; mt++) {
                const int row = wm * 64 + mt * 16 + lrow;
                ldsm_x4(a[mt][0], a[mt][1], a[mt][2], a[mt][3],
                        a_s + swz(row * 128 + kb));
            }
#pragma unroll
            for (int bt = 0; bt < 2; bt++) {
                const int row = wn * 32 + bt * 16 + lrow;
                uint32_t r0, r1, r2, r3;
                ldsm_x4(r0, r1, r2, r3, b_s + swz(row * 128 + kb));
                b[bt * 2 + 0][0] = r0; b[bt * 2 + 1][0] = r1;
                b[bt * 2 + 0][1] = r2; b[bt * 2 + 1][1] = r3;
            }
#pragma unroll
            for (int mt = 0; mt < 4; mt++)
#pragma unroll
                for (int nt = 0; nt < 4; nt++)
                    mma_f16(acc[mt][nt], a[mt], b[nt]);
        }
        __syncthreads();
        if (i + 3 < NITER) issue_loads(i + 3);
        CP_COMMIT();
    }

    // ---- epilogue ----
    const int g = lane >> 2, t4 = lane & 3;
#pragma unroll
    for (int mt = 0; mt < 4; mt++) {
#pragma unroll
        for (int nt = 0; nt < 4; nt++) {
            const int rm = by * 128 + wm * 64 + mt * 16 + g;
            const int cg = bx * 128 + wn * 32 + nt * 8 + t4 * 2;
            const float b0 = __ldg(&bias[cg]);
            const float b1 = __ldg(&bias[cg + 1]);
            float v0 = acc[mt][nt][0] + b0;
            float v1 = acc[mt][nt][1] + b1;
            float v2 = acc[mt][nt][2] + b0;
            float v3 = acc[mt][nt][3] + b1;
            if (GELU) {
                v0 = 0.5f * v0 * (1.0f + erff(v0 * 0.70710678118654752f));
                v1 = 0.5f * v1 * (1.0f + erff(v1 * 0.70710678118654752f));
                v2 = 0.5f * v2 * (1.0f + erff(v2 * 0.70710678118654752f));
                v3 = 0.5f * v3 * (1.0f + erff(v3 * 0.70710678118654752f));
            }
            if (PERM) {
                const int nh = cg >> 8, ij = cg & 255;
                const int b_ = rm >> 11, t_ = rm & (TLEN - 1);
                float* o = C + (((size_t)(b_ * 16 + nh) * TLEN + t_) * 256 + ij);
                *(float2*)o = make_float2(v0, v1);
                *(float2*)(o + 8 * 256) = make_float2(v2, v3);
            } else {
                float* o = C + ((size_t)rm * NDIM + cg);
                *(float2*)o = make_float2(v0, v1);
                *(float2*)(o + (size_t)8 * NDIM) = make_float2(v2, v3);
            }
        }
    }
}

// ---------------------------------------------------------------------------
// In-place Frobenius normalization: one warp per 16x16 matrix.
// ---------------------------------------------------------------------------
__global__ __launch_bounds__(256)
void fro_norm_kernel(float* __restrict__ m)
{
    const size_t mat = (size_t)blockIdx.x * 8 + (threadIdx.x >> 5);
    const int lane = threadIdx.x & 31;
    float* p = m + mat * 256 + lane * 8;
    float4 a = *(float4*)p;
    float4 b = *(float4*)(p + 4);
    float ss = a.x * a.x + a.y * a.y + a.z * a.z + a.w * a.w
             + b.x * b.x + b.y * b.y + b.z * b.z + b.w * b.w;
    ss += __shfl_xor_sync(0xffffffffu, ss, 16);
    ss += __shfl_xor_sync(0xffffffffu, ss, 8);
    ss += __shfl_xor_sync(0xffffffffu, ss, 4);
    ss += __shfl_xor_sync(0xffffffffu, ss, 2);
    ss += __shfl_xor_sync(0xffffffffu, ss, 1);
    const float sc = 4.0f / (sqrtf(ss) + 1e-5f);
    a.x *= sc; a.y *= sc; a.z *= sc; a.w *= sc;
    b.x *= sc; b.y *= sc; b.z *= sc; b.w *= sc;
    *(float4*)p = a;
    *(float4*)(p + 4) = b;
}

// ---------------------------------------------------------------------------
// Sequential scan with DEEP REGISTER PREFETCH (ring of 8 matrices, MLP=8
// covers ~577cyc DRAM latency) + deferred normalization (rescale every 4th).
// One warp per (sequence, direction). Grid 256 x 32 threads.
// ---------------------------------------------------------------------------
#define PF 8

__global__ __launch_bounds__(32)
void scan_kernel(const float* __restrict__ mn, __half* __restrict__ xh,
                 __half* __restrict__ xl)
{
    const unsigned F = 0xffffffffu;
    const int lane = threadIdx.x & 31;
    const int s = blockIdx.x & 127;        // sequence (b*16+nh)
    const int d = blockIdx.x >> 7;         // 0 = lr, 1 = rl
    const int b = s >> 4;
    const int nh = s & 15;

    const int laneoff = (lane & 15) * 16 + (lane >> 4) * 8;
    const float* base = mn + (size_t)s * (TLEN * 256) + laneoff;
    const int h8 = (lane >> 4) << 3;

    const int t0 = d ? (TLEN - 1) : 0;
    const int dt = d ? -1 : 1;

    float u = ((lane & 15) == 0) ? 1.0f : 0.0f;
    const size_t xoff = (size_t)b * TLEN * 512 + nh * 32 + d * 16 + (lane & 15);

    float4 r0[PF], r1[PF];
#pragma unroll
    for (int j = 0; j < PF; j++) {
        const int tj = t0 + j * dt;             // always in range (PF <= TLEN)
        const float* q = base + (size_t)tj * 256;
        r0[j] = __ldg((const float4*)q);
        r1[j] = __ldg((const float4*)(q + 4));
    }

#pragma unroll 1
    for (int blk = 0; blk < TLEN / PF; ++blk) {
#pragma unroll
        for (int sub = 0; sub < PF; ++sub) {
            const int step = blk * PF + sub;
            const int t = t0 + step * dt;

            const float4 c0 = r0[sub];
            const float4 c1 = r1[sub];

            // prefetch step+PF into this slot (clamped; unused past the end)
            int tp = t + PF * dt;
            tp = tp < 0 ? 0 : (tp > TLEN - 1 ? TLEN - 1 : tp);
            const float* q = base + (size_t)tp * 256;
            r0[sub] = __ldg((const float4*)q);
            r1[sub] = __ldg((const float4*)(q + 4));

            const float vb0 = __shfl_sync(F, u, h8 + 0);
            const float vb1 = __shfl_sync(F, u, h8 + 1);
            const float vb2 = __shfl_sync(F, u, h8 + 2);
            const float vb3 = __shfl_sync(F, u, h8 + 3);
            const float vb4 = __shfl_sync(F, u, h8 + 4);
            const float vb5 = __shfl_sync(F, u, h8 + 5);
            const float vb6 = __shfl_sync(F, u, h8 + 6);
            const float vb7 = __shfl_sync(F, u, h8 + 7);

            float pA = c0.x * vb0;
            pA = fmaf(c0.y, vb1, pA);
            pA = fmaf(c0.z, vb2, pA);
            pA = fmaf(c0.w, vb3, pA);
            float pB = c1.x * vb4;
            pB = fmaf(c1.y, vb5, pB);
            pB = fmaf(c1.z, vb6, pB);
            pB = fmaf(c1.w, vb7, pB);
            const float pp = pA + pB;

            const float nv = pp + __shfl_xor_sync(F, pp, 16);

            // off-critical-path: norm + normalized output
            float ss = nv * nv;
            ss += __shfl_xor_sync(F, ss, 8);
            ss += __shfl_xor_sync(F, ss, 4);
            ss += __shfl_xor_sync(F, ss, 2);
            ss += __shfl_xor_sync(F, ss, 1);
            const float w = nv / (sqrtf(ss) + 1e-6f);

            if (lane < 16) {
                __half h, l;
                split_f16(w, h, l);
                xh[xoff + (size_t)t * 512] = h;
                xl[xoff + (size_t)t * 512] = l;
            }

            // rescale every 4th step (static select keeps sqrt/div off the
            // recurrence path on other steps)
            u = ((sub & 3) == 3) ? w : nv;
        }
    }
}

// ---------------------------------------------------------------------------
// Launch
// ---------------------------------------------------------------------------
extern "C" void kernel_launch(void* const* d_in, const int* in_sizes, int n_in,
                              void* d_out, int out_size)
{
    const float* hs = (const float*)d_in[0];
    const float* Wm = (const float*)d_in[1];
    const float* bm = (const float*)d_in[2];
    const float* Wo = (const float*)d_in[3];
    const float* bo = (const float*)d_in[4];
    float* out = (float*)d_out;

    float* pm;
    __half *pah, *pal, *pbh, *pbl, *pxh, *pxl, *pwh, *pwl;
    cudaGetSymbolAddress((void**)&pm, g_m);
    cudaGetSymbolAddress((void**)&pah, g_ah);
    cudaGetSymbolAddress((void**)&pal, g_al);
    cudaGetSymbolAddress((void**)&pbh, g_bh);
    cudaGetSymbolAddress((void**)&pbl, g_bl);
    cudaGetSymbolAddress((void**)&pxh, g_xh);
    cudaGetSymbolAddress((void**)&pxl, g_xl);
    cudaGetSymbolAddress((void**)&pwh, g_wh);
    cudaGetSymbolAddress((void**)&pwl, g_wl);

    // 0) fp16 splits
    convA_kernel<<<(BT * HIDD / 4) / 256, 256>>>(hs, pah, pal);
    convW_kernel<<<dim3(N1 / 32, HIDD / 32), dim3(32, 32)>>>(Wm, pbh, pbl, HIDD, N1);
    convW_kernel<<<dim3(HIDD / 32, K2D / 32), dim3(32, 32)>>>(Wo, pwh, pwl, K2D, HIDD);

    // 1) GEMM1 (HMMA fp16 split) -> scan layout (+bias)
    cudaFuncSetAttribute(gemm_mma_kernel<true, false, HIDD, N1>,
                         cudaFuncAttributeMaxDynamicSharedMemorySize, GEMM_SMEM);
    gemm_mma_kernel<true, false, HIDD, N1>
        <<<dim3(N1 / 128, BT / 128), 256, GEMM_SMEM>>>(pah, pal, pbh, pbl, bm, pm);

    // 2) In-place Frobenius normalization
    fro_norm_kernel<<<(BT * NHH) / 8, 256>>>(pm);

    // 3) Bidirectional scan (deep prefetch + deferred norm) -> fp16 hi/lo
    scan_kernel<<<256, 32>>>(pm, pxh, pxl);

    // 4) GEMM2 (HMMA fp16 split): out = gelu(x @ W_out + b_out)
    cudaFuncSetAttribute(gemm_mma_kernel<false, true, K2D, HIDD>,
                         cudaFuncAttributeMaxDynamicSharedMemorySize, GEMM_SMEM);
    gemm_mma_kernel<false, true, K2D, HIDD>
        <<<dim3(HIDD / 128, BT / 128), 256, GEMM_SMEM>>>(pxh, pxl, pwh, pwl, bo, out);
}

// round 11
// speedup vs baseline: 2.4555x; 1.0160x over previous
#include <cuda_runtime.h>
#include <cuda_fp16.h>
#include <cstdint>
#include <math.h>

// Problem constants
#define BB     8
#define TLEN   2048
#define HIDD   1024
#define NHH    16
#define MDD    16
#define BT     (BB * TLEN)          // 16384 rows
#define N1     (NHH * MDD * MDD)    // 4096
#define K2D    (NHH * MDD * 2)      // 512

// ---------------------------------------------------------------------------
// Scratch (device globals — no allocation allowed)
// ---------------------------------------------------------------------------
__device__ float  g_m[(size_t)BT * N1];               // scan layout [s][t][256] (UNNORMALIZED)
__device__ __half g_ah[(size_t)BT * HIDD];            // hs hi
__device__ __half g_al[(size_t)BT * HIDD];            // hs lo (unscaled)
__device__ __half g_bh[(size_t)N1 * HIDD];            // W_mat^T hi  [n][k]
__device__ __half g_bl[(size_t)N1 * HIDD];            // W_mat^T lo  [n][k]
__device__ __half g_xh[(size_t)BT * K2D];             // scan out hi
__device__ __half g_xl[(size_t)BT * K2D];             // scan out lo
__device__ __half g_wh[(size_t)HIDD * K2D];           // W_out^T hi [n][k]
__device__ __half g_wl[(size_t)HIDD * K2D];           // W_out^T lo [n][k]

// ---------------------------------------------------------------------------
// Helpers
// ---------------------------------------------------------------------------
__device__ __forceinline__ uint32_t smem_u32(const void* p) {
    uint32_t a;
    asm("{ .reg .u64 t; cvta.to.shared.u64 t, %1; cvt.u32.u64 %0, t; }" : "=r"(a) : "l"(p));
    return a;
}
#define CP_ASYNC16(dst, src) \
    asm volatile("cp.async.cg.shared.global [%0], [%1], 16;\n" :: "r"(dst), "l"(src) : "memory")
#define CP_COMMIT()  asm volatile("cp.async.commit_group;\n" ::: "memory")
#define CP_WAIT1()   asm volatile("cp.async.wait_group 1;\n" ::: "memory")

__device__ __forceinline__ void ldsm_x4(uint32_t& r0, uint32_t& r1, uint32_t& r2,
                                        uint32_t& r3, uint32_t addr) {
    asm volatile("ldmatrix.sync.aligned.m8n8.x4.shared.b16 {%0,%1,%2,%3}, [%4];"
                 : "=r"(r0), "=r"(r1), "=r"(r2), "=r"(r3) : "r"(addr));
}
__device__ __forceinline__ void mma_f16(float* c, const uint32_t* a, const uint32_t* b) {
    asm volatile(
        "mma.sync.aligned.m16n8k16.row.col.f32.f16.f16.f32 "
        "{%0,%1,%2,%3}, {%4,%5,%6,%7}, {%8,%9}, {%0,%1,%2,%3};"
        : "+f"(c[0]), "+f"(c[1]), "+f"(c[2]), "+f"(c[3])
        : "r"(a[0]), "r"(a[1]), "r"(a[2]), "r"(a[3]), "r"(b[0]), "r"(b[1]));
}
__device__ __forceinline__ uint32_t swz(uint32_t off) { return off ^ ((off >> 3) & 0x70); }

__device__ __forceinline__ void split_f16(float a, __half& h, __half& l) {
    h = __float2half_rn(a);
    l = __float2half_rn(a - __half2float(h));   // unscaled residual (may be subnormal)
}

// ---------------------------------------------------------------------------
// Conversion kernels
// ---------------------------------------------------------------------------
struct alignas(8) h4 { __half v[4]; };

__global__ __launch_bounds__(256)
void convA_kernel(const float* __restrict__ x, __half* __restrict__ hi,
                  __half* __restrict__ lo)
{
    const int i = blockIdx.x * blockDim.x + threadIdx.x;   // float4 index
    float4 v = ((const float4*)x)[i];
    h4 h, l;
    float a[4] = {v.x, v.y, v.z, v.w};
#pragma unroll
    for (int j = 0; j < 4; j++) split_f16(a[j], h.v[j], l.v[j]);
    ((h4*)hi)[i] = h;
    ((h4*)lo)[i] = l;
}

// Transpose W (KR x NC, row-major) -> [n][k] fp16 hi/lo
__global__ __launch_bounds__(1024)
void convW_kernel(const float* __restrict__ W, __half* __restrict__ wh,
                  __half* __restrict__ wl, int KR, int NC)
{
    __shared__ float tile[32][33];
    const int n_in = blockIdx.x * 32 + threadIdx.x;
    const int k_in = blockIdx.y * 32 + threadIdx.y;
    tile[threadIdx.y][threadIdx.x] = W[(size_t)k_in * NC + n_in];
    __syncthreads();
    const int n_out = blockIdx.x * 32 + threadIdx.y;
    const int k_out = blockIdx.y * 32 + threadIdx.x;
    const float v = tile[threadIdx.x][threadIdx.y];
    __half h, l;
    split_f16(v, h, l);
    const size_t o = (size_t)n_out * KR + k_out;
    wh[o] = h;
    wl[o] = l;
}

// ---------------------------------------------------------------------------
// HMMA GEMM, fp16 2-term split, single fp32 accumulator:
//   D = Ah*Bl + Al*Bh + Ah*Bh   [+ bias]
// CTA tile 128x128, 8 warps (2m x 4n), warp tile 64x32.
// 3-stage cp.async ring, SINGLE __syncthreads per chunk:
//   prologue fills 2 stages; iter i: wait_group1 (stage i done) -> sync ->
//   issue stage (i+2)%3 (== stage consumed at iter i-1; safe because every
//   warp passed this sync only after finishing iter i-1's compute) -> compute.
// ---------------------------------------------------------------------------
#define STAGE_BYTES 32768            // A 16KB + B 16KB
#define GEMM_SMEM   (1024 + 3 * STAGE_BYTES)

template <bool PERM, bool GELU, int KDIM, int NDIM>
__global__ __launch_bounds__(256, 2)
void gemm_mma_kernel(const __half* __restrict__ Ah, const __half* __restrict__ Al,
                     const __half* __restrict__ Bh, const __half* __restrict__ Bl,
                     const float* __restrict__ bias, float* __restrict__ C)
{
    constexpr int CHUNKS = KDIM / 64;
    constexpr int NITER  = 3 * CHUNKS;

    extern __shared__ char smem[];
    const uint32_t tiles = (smem_u32(smem) + 1023u) & ~1023u;
    const int tid = threadIdx.x;
    const int lane = tid & 31, warp = tid >> 5;
    const int wm = warp & 1, wn = warp >> 1;     // 2 x 4 warp grid
    const int bx = blockIdx.x;                   // N tile
    const int by = blockIdx.y;                   // M tile

    // small terms first, dominant product last
    const __half* Asrc[3] = {Ah, Al, Ah};
    const __half* Bsrc[3] = {Bl, Bh, Bh};

    const int lr = tid >> 3;           // 0..31
    const int lc = (tid & 7) * 16;     // byte col in 128B row

    auto issue_loads = [&](int iter) {
        const int pass = iter / CHUNKS, chunk = iter % CHUNKS, stage = iter % 3;
        const uint32_t a_s = tiles + stage * STAGE_BYTES;
        const uint32_t b_s = a_s + 16384;
        const __half* Ap = Asrc[pass] + (size_t)(by * 128) * KDIM + chunk * 64 + (lc >> 1);
        const __half* Bp = Bsrc[pass] + (size_t)(bx * 128) * KDIM + chunk * 64 + (lc >> 1);
#pragma unroll
        for (int it = 0; it < 4; it++) {
            const int row = it * 32 + lr;
            CP_ASYNC16(a_s + swz(row * 128 + lc), Ap + (size_t)row * KDIM);
        }
#pragma unroll
        for (int it = 0; it < 4; it++) {
            const int row = it * 32 + lr;
            CP_ASYNC16(b_s + swz(row * 128 + lc), Bp + (size_t)row * KDIM);
        }
    };

    float acc[4][4][4];
#pragma unroll
    for (int i = 0; i < 4; i++)
#pragma unroll
        for (int j = 0; j < 4; j++)
#pragma unroll
            for (int k = 0; k < 4; k++) acc[i][j][k] = 0.0f;

    const int lrow = lane & 15;
    const int lkof = (lane >> 4) * 16;

    for (int j = 0; j < 2; j++) { issue_loads(j); CP_COMMIT(); }

    for (int i = 0; i < NITER; i++) {
        CP_WAIT1();                     // stage i's group complete
        __syncthreads();                // data visible to all; iter i-1 compute done
        if (i + 2 < NITER) issue_loads(i + 2);   // into stage (i-1)%3 — safe
        CP_COMMIT();                    // unconditional: keeps group counting uniform

        const uint32_t a_s = tiles + (i % 3) * STAGE_BYTES;
        const uint32_t b_s = a_s + 16384;

#pragma unroll
        for (int ks = 0; ks < 4; ks++) {
            const int kb = ks * 32 + lkof;
            uint32_t a[4][4], b[4][2];
#pragma unroll
            for (int mt = 0; mt < 4; mt++) {
                const int row = wm * 64 + mt * 16 + lrow;
                ldsm_x4(a[mt][0], a[mt][1], a[mt][2], a[mt][3],
                        a_s + swz(row * 128 + kb));
            }
#pragma unroll
            for (int bt = 0; bt < 2; bt++) {
                const int row = wn * 32 + bt * 16 + lrow;
                uint32_t r0, r1, r2, r3;
                ldsm_x4(r0, r1, r2, r3, b_s + swz(row * 128 + kb));
                b[bt * 2 + 0][0] = r0; b[bt * 2 + 1][0] = r1;
                b[bt * 2 + 0][1] = r2; b[bt * 2 + 1][1] = r3;
            }
#pragma unroll
            for (int mt = 0; mt < 4; mt++)
#pragma unroll
                for (int nt = 0; nt < 4; nt++)
                    mma_f16(acc[mt][nt], a[mt], b[nt]);
        }
    }

    // ---- epilogue ----
    const int g = lane >> 2, t4 = lane & 3;
#pragma unroll
    for (int mt = 0; mt < 4; mt++) {
#pragma unroll
        for (int nt = 0; nt < 4; nt++) {
            const int rm = by * 128 + wm * 64 + mt * 16 + g;
            const int cg = bx * 128 + wn * 32 + nt * 8 + t4 * 2;
            const float b0 = __ldg(&bias[cg]);
            const float b1 = __ldg(&bias[cg + 1]);
            float v0 = acc[mt][nt][0] + b0;
            float v1 = acc[mt][nt][1] + b1;
            float v2 = acc[mt][nt][2] + b0;
            float v3 = acc[mt][nt][3] + b1;
            if (GELU) {
                v0 = 0.5f * v0 * (1.0f + erff(v0 * 0.70710678118654752f));
                v1 = 0.5f * v1 * (1.0f + erff(v1 * 0.70710678118654752f));
                v2 = 0.5f * v2 * (1.0f + erff(v2 * 0.70710678118654752f));
                v3 = 0.5f * v3 * (1.0f + erff(v3 * 0.70710678118654752f));
            }
            if (PERM) {
                const int nh = cg >> 8, ij = cg & 255;
                const int b_ = rm >> 11, t_ = rm & (TLEN - 1);
                float* o = C + (((size_t)(b_ * 16 + nh) * TLEN + t_) * 256 + ij);
                *(float2*)o = make_float2(v0, v1);
                *(float2*)(o + 8 * 256) = make_float2(v2, v3);
            } else {
                float* o = C + ((size_t)rm * NDIM + cg);
                *(float2*)o = make_float2(v0, v1);
                *(float2*)(o + (size_t)8 * NDIM) = make_float2(v2, v3);
            }
        }
    }
}

// ---------------------------------------------------------------------------
// Sequential scan on UNNORMALIZED matrices. The per-step vector
// normalization w = nv/(||nv||+1e-6) is scale-invariant in M, so the
// reference's Frobenius matrix normalization (a positive per-matrix scalar)
// is dropped entirely — its only trace is the eps weighting (~1e-5 relative,
// negligible). Deep register prefetch (ring of 8, MLP=8) + deferred vector
// normalization (rescale every 4th step keeps fp32 range: growth <~30/block).
// One warp per (sequence, direction). Grid 256 x 32 threads.
// ---------------------------------------------------------------------------
#define PF 8

__global__ __launch_bounds__(32)
void scan_kernel(const float* __restrict__ mn, __half* __restrict__ xh,
                 __half* __restrict__ xl)
{
    const unsigned F = 0xffffffffu;
    const int lane = threadIdx.x & 31;
    const int s = blockIdx.x & 127;        // sequence (b*16+nh)
    const int d = blockIdx.x >> 7;         // 0 = lr, 1 = rl
    const int b = s >> 4;
    const int nh = s & 15;

    const int laneoff = (lane & 15) * 16 + (lane >> 4) * 8;
    const float* base = mn + (size_t)s * (TLEN * 256) + laneoff;
    const int h8 = (lane >> 4) << 3;

    const int t0 = d ? (TLEN - 1) : 0;
    const int dt = d ? -1 : 1;

    float u = ((lane & 15) == 0) ? 1.0f : 0.0f;
    const size_t xoff = (size_t)b * TLEN * 512 + nh * 32 + d * 16 + (lane & 15);

    float4 r0[PF], r1[PF];
#pragma unroll
    for (int j = 0; j < PF; j++) {
        const int tj = t0 + j * dt;
        const float* q = base + (size_t)tj * 256;
        r0[j] = __ldg((const float4*)q);
        r1[j] = __ldg((const float4*)(q + 4));
    }

#pragma unroll 1
    for (int blk = 0; blk < TLEN / PF; ++blk) {
#pragma unroll
        for (int sub = 0; sub < PF; ++sub) {
            const int step = blk * PF + sub;
            const int t = t0 + step * dt;

            const float4 c0 = r0[sub];
            const float4 c1 = r1[sub];

            // prefetch step+PF into this slot (clamped; unused past the end)
            int tp = t + PF * dt;
            tp = tp < 0 ? 0 : (tp > TLEN - 1 ? TLEN - 1 : tp);
            const float* q = base + (size_t)tp * 256;
            r0[sub] = __ldg((const float4*)q);
            r1[sub] = __ldg((const float4*)(q + 4));

            const float vb0 = __shfl_sync(F, u, h8 + 0);
            const float vb1 = __shfl_sync(F, u, h8 + 1);
            const float vb2 = __shfl_sync(F, u, h8 + 2);
            const float vb3 = __shfl_sync(F, u, h8 + 3);
            const float vb4 = __shfl_sync(F, u, h8 + 4);
            const float vb5 = __shfl_sync(F, u, h8 + 5);
            const float vb6 = __shfl_sync(F, u, h8 + 6);
            const float vb7 = __shfl_sync(F, u, h8 + 7);

            float pA = c0.x * vb0;
            pA = fmaf(c0.y, vb1, pA);
            pA = fmaf(c0.z, vb2, pA);
            pA = fmaf(c0.w, vb3, pA);
            float pB = c1.x * vb4;
            pB = fmaf(c1.y, vb5, pB);
            pB = fmaf(c1.z, vb6, pB);
            pB = fmaf(c1.w, vb7, pB);
            const float pp = pA + pB;

            const float nv = pp + __shfl_xor_sync(F, pp, 16);

            // off-critical-path: norm + normalized output
            float ss = nv * nv;
            ss += __shfl_xor_sync(F, ss, 8);
            ss += __shfl_xor_sync(F, ss, 4);
            ss += __shfl_xor_sync(F, ss, 2);
            ss += __shfl_xor_sync(F, ss, 1);
            const float w = nv / (sqrtf(ss) + 1e-6f);

            if (lane < 16) {
                __half h, l;
                split_f16(w, h, l);
                xh[xoff + (size_t)t * 512] = h;
                xl[xoff + (size_t)t * 512] = l;
            }

            // rescale every 4th step (static select keeps sqrt/div off the
            // recurrence path on other steps)
            u = ((sub & 3) == 3) ? w : nv;
        }
    }
}

// ---------------------------------------------------------------------------
// Launch
// ---------------------------------------------------------------------------
extern "C" void kernel_launch(void* const* d_in, const int* in_sizes, int n_in,
                              void* d_out, int out_size)
{
    const float* hs = (const float*)d_in[0];
    const float* Wm = (const float*)d_in[1];
    const float* bm = (const float*)d_in[2];
    const float* Wo = (const float*)d_in[3];
    const float* bo = (const float*)d_in[4];
    float* out = (float*)d_out;

    float* pm;
    __half *pah, *pal, *pbh, *pbl, *pxh, *pxl, *pwh, *pwl;
    cudaGetSymbolAddress((void**)&pm, g_m);
    cudaGetSymbolAddress((void**)&pah, g_ah);
    cudaGetSymbolAddress((void**)&pal, g_al);
    cudaGetSymbolAddress((void**)&pbh, g_bh);
    cudaGetSymbolAddress((void**)&pbl, g_bl);
    cudaGetSymbolAddress((void**)&pxh, g_xh);
    cudaGetSymbolAddress((void**)&pxl, g_xl);
    cudaGetSymbolAddress((void**)&pwh, g_wh);
    cudaGetSymbolAddress((void**)&pwl, g_wl);

    // 0) fp16 splits
    convA_kernel<<<(BT * HIDD / 4) / 256, 256>>>(hs, pah, pal);
    convW_kernel<<<dim3(N1 / 32, HIDD / 32), dim3(32, 32)>>>(Wm, pbh, pbl, HIDD, N1);
    convW_kernel<<<dim3(HIDD / 32, K2D / 32), dim3(32, 32)>>>(Wo, pwh, pwl, K2D, HIDD);

    // 1) GEMM1 (HMMA fp16 split) -> scan layout (+bias), UNNORMALIZED
    cudaFuncSetAttribute(gemm_mma_kernel<true, false, HIDD, N1>,
                         cudaFuncAttributeMaxDynamicSharedMemorySize, GEMM_SMEM);
    gemm_mma_kernel<true, false, HIDD, N1>
        <<<dim3(N1 / 128, BT / 128), 256, GEMM_SMEM>>>(pah, pal, pbh, pbl, bm, pm);

    // 2) Bidirectional scan (scale-invariant; fro-norm eliminated) -> fp16 hi/lo
    scan_kernel<<<256, 32>>>(pm, pxh, pxl);

    // 3) GEMM2 (HMMA fp16 split): out = gelu(x @ W_out + b_out)
    cudaFuncSetAttribute(gemm_mma_kernel<false, true, K2D, HIDD>,
                         cudaFuncAttributeMaxDynamicSharedMemorySize, GEMM_SMEM);
    gemm_mma_kernel<false, true, K2D, HIDD>
        <<<dim3(HIDD / 128, BT / 128), 256, GEMM_SMEM>>>(pxh, pxl, pwh, pwl, bo, out);
}

// round 12
// speedup vs baseline: 2.5006x; 1.0184x over previous
#include <cuda_runtime.h>
#include <cuda_fp16.h>
#include <cstdint>
#include <math.h>

// Problem constants
#define BB     8
#define TLEN   2048
#define HIDD   1024
#define NHH    16
#define MDD    16
#define BT     (BB * TLEN)          // 16384 rows
#define N1     (NHH * MDD * MDD)    // 4096
#define K2D    (NHH * MDD * 2)      // 512

// ---------------------------------------------------------------------------
// Scratch (device globals — no allocation allowed)
// ---------------------------------------------------------------------------
__device__ float  g_m[(size_t)BT * N1];               // scan layout [s][t][256] (UNNORMALIZED)
__device__ __half g_ah[(size_t)BT * HIDD];            // hs hi
__device__ __half g_al[(size_t)BT * HIDD];            // hs lo (unscaled)
__device__ __half g_bh[(size_t)N1 * HIDD];            // W_mat^T hi  [n][k]
__device__ __half g_bl[(size_t)N1 * HIDD];            // W_mat^T lo  [n][k]
__device__ __half g_xh[(size_t)BT * K2D];             // scan out hi
__device__ __half g_xl[(size_t)BT * K2D];             // scan out lo
__device__ __half g_wh[(size_t)HIDD * K2D];           // W_out^T hi [n][k]
__device__ __half g_wl[(size_t)HIDD * K2D];           // W_out^T lo [n][k]

// ---------------------------------------------------------------------------
// Helpers
// ---------------------------------------------------------------------------
__device__ __forceinline__ uint32_t smem_u32(const void* p) {
    uint32_t a;
    asm("{ .reg .u64 t; cvta.to.shared.u64 t, %1; cvt.u32.u64 %0, t; }" : "=r"(a) : "l"(p));
    return a;
}
#define CP_ASYNC16(dst, src) \
    asm volatile("cp.async.cg.shared.global [%0], [%1], 16;\n" :: "r"(dst), "l"(src) : "memory")
#define CP_COMMIT()  asm volatile("cp.async.commit_group;\n" ::: "memory")
#define CP_WAIT1()   asm volatile("cp.async.wait_group 1;\n" ::: "memory")

__device__ __forceinline__ void ldsm_x4(uint32_t& r0, uint32_t& r1, uint32_t& r2,
                                        uint32_t& r3, uint32_t addr) {
    asm volatile("ldmatrix.sync.aligned.m8n8.x4.shared.b16 {%0,%1,%2,%3}, [%4];"
                 : "=r"(r0), "=r"(r1), "=r"(r2), "=r"(r3) : "r"(addr));
}
__device__ __forceinline__ void mma_f16(float* c, const uint32_t* a, const uint32_t* b) {
    asm volatile(
        "mma.sync.aligned.m16n8k16.row.col.f32.f16.f16.f32 "
        "{%0,%1,%2,%3}, {%4,%5,%6,%7}, {%8,%9}, {%0,%1,%2,%3};"
        : "+f"(c[0]), "+f"(c[1]), "+f"(c[2]), "+f"(c[3])
        : "r"(a[0]), "r"(a[1]), "r"(a[2]), "r"(a[3]), "r"(b[0]), "r"(b[1]));
}
__device__ __forceinline__ uint32_t swz(uint32_t off)   { return off ^ ((off >> 3) & 0x70); } // SW128
__device__ __forceinline__ uint32_t swz64(uint32_t off) { return off ^ ((off >> 3) & 0x30); } // SW64

__device__ __forceinline__ void split_f16(float a, __half& h, __half& l) {
    h = __float2half_rn(a);
    l = __float2half_rn(a - __half2float(h));
}

// ---------------------------------------------------------------------------
// Conversion kernels
// ---------------------------------------------------------------------------
struct alignas(8) h4 { __half v[4]; };

__global__ __launch_bounds__(256)
void convA_kernel(const float* __restrict__ x, __half* __restrict__ hi,
                  __half* __restrict__ lo)
{
    const int i = blockIdx.x * blockDim.x + threadIdx.x;
    float4 v = ((const float4*)x)[i];
    h4 h, l;
    float a[4] = {v.x, v.y, v.z, v.w};
#pragma unroll
    for (int j = 0; j < 4; j++) split_f16(a[j], h.v[j], l.v[j]);
    ((h4*)hi)[i] = h;
    ((h4*)lo)[i] = l;
}

// Transpose W (KR x NC, row-major) -> [n][k] fp16 hi/lo
__global__ __launch_bounds__(1024)
void convW_kernel(const float* __restrict__ W, __half* __restrict__ wh,
                  __half* __restrict__ wl, int KR, int NC)
{
    __shared__ float tile[32][33];
    const int n_in = blockIdx.x * 32 + threadIdx.x;
    const int k_in = blockIdx.y * 32 + threadIdx.y;
    tile[threadIdx.y][threadIdx.x] = W[(size_t)k_in * NC + n_in];
    __syncthreads();
    const int n_out = blockIdx.x * 32 + threadIdx.y;
    const int k_out = blockIdx.y * 32 + threadIdx.x;
    const float v = tile[threadIdx.x][threadIdx.y];
    __half h, l;
    split_f16(v, h, l);
    const size_t o = (size_t)n_out * KR + k_out;
    wh[o] = h;
    wl[o] = l;
}

// ---------------------------------------------------------------------------
// GEMM1, FUSED-CHUNK fp16 split: per K-chunk (32 halfs) load Ah/Al/Bh/Bl
// tiles once, compute Ah*Bl + Ah*Bh + Al*Bh with register fragment reuse
// (Ah reused across 2 products, Bh across 2). 33% less smem traffic than the
// pass-based loop. SW64 swizzle (64B rows). 3-stage ring, 2 CTAs/SM.
// CTA tile 128x128, 8 warps (2m x 4n), warp tile 64x32.
// ---------------------------------------------------------------------------
#define CH_K     32                         // halfs per chunk
#define TILE_B   8192                       // 128 rows * 64 bytes
#define ST_B     (4 * TILE_B)               // 32KB per stage (Ah,Al,Bh,Bl)
#define G1_SMEM  (1024 + 3 * ST_B)
#define NCHUNK   (HIDD / CH_K)              // 32

__global__ __launch_bounds__(256, 2)
void gemm1_fused_kernel(const __half* __restrict__ Ah, const __half* __restrict__ Al,
                        const __half* __restrict__ Bh, const __half* __restrict__ Bl,
                        const float* __restrict__ bias, float* __restrict__ C)
{
    extern __shared__ char smem[];
    const uint32_t tiles = (smem_u32(smem) + 1023u) & ~1023u;
    const int tid = threadIdx.x;
    const int lane = tid & 31, warp = tid >> 5;
    const int wm = warp & 1, wn = warp >> 1;     // 2 x 4 warp grid
    const int bx = blockIdx.x;                   // N tile (0..31)
    const int by = blockIdx.y;                   // M tile (0..127)

    // cp.async: 256 threads, 16B each; per tile 512 ops -> 2 per thread
    const int lr  = tid >> 2;          // 0..63 (row)
    const int lcb = (tid & 3) * 16;    // byte col within 64B row

    const __half* Asrcs[2] = {Ah, Al};
    const __half* Bsrcs[2] = {Bh, Bl};

    auto issue_loads = [&](int chunk) {
        const int stage = chunk % 3;
        const uint32_t s = tiles + stage * ST_B;
        const int koff = chunk * CH_K + (lcb >> 1);
#pragma unroll
        for (int a = 0; a < 2; a++) {
            const __half* Ap = Asrcs[a] + (size_t)(by * 128 + lr) * HIDD + koff;
            const uint32_t d = s + a * TILE_B;
            CP_ASYNC16(d + swz64(lr * 64 + lcb), Ap);
            CP_ASYNC16(d + swz64((lr + 64) * 64 + lcb), Ap + (size_t)64 * HIDD);
        }
#pragma unroll
        for (int b = 0; b < 2; b++) {
            const __half* Bp = Bsrcs[b] + (size_t)(bx * 128 + lr) * HIDD + koff;
            const uint32_t d = s + (2 + b) * TILE_B;
            CP_ASYNC16(d + swz64(lr * 64 + lcb), Bp);
            CP_ASYNC16(d + swz64((lr + 64) * 64 + lcb), Bp + (size_t)64 * HIDD);
        }
    };

    float acc[4][4][4];
#pragma unroll
    for (int i = 0; i < 4; i++)
#pragma unroll
        for (int j = 0; j < 4; j++)
#pragma unroll
            for (int k = 0; k < 4; k++) acc[i][j][k] = 0.0f;

    const int lrow = lane & 15;
    const int lkof = (lane >> 4) * 16;

    issue_loads(0); CP_COMMIT();
    issue_loads(1); CP_COMMIT();

    for (int i = 0; i < NCHUNK; i++) {
        CP_WAIT1();
        __syncthreads();
        if (i + 2 < NCHUNK) issue_loads(i + 2);
        CP_COMMIT();

        const uint32_t s   = tiles + (i % 3) * ST_B;
        const uint32_t a_h = s;
        const uint32_t a_l = s + TILE_B;
        const uint32_t b_h = s + 2 * TILE_B;
        const uint32_t b_l = s + 3 * TILE_B;

#pragma unroll
        for (int ks = 0; ks < 2; ks++) {
            const int kb = ks * 32 + lkof;      // byte col: {0,16} or {32,48}

            // --- Ah fragments (reused for 2 products) ---
            uint32_t ahf[4][4];
#pragma unroll
            for (int mt = 0; mt < 4; mt++) {
                const int row = wm * 64 + mt * 16 + lrow;
                ldsm_x4(ahf[mt][0], ahf[mt][1], ahf[mt][2], ahf[mt][3],
                        a_h + swz64(row * 64 + kb));
            }
            // --- Bl fragments, product Ah*Bl ---
            {
                uint32_t blf[4][2];
#pragma unroll
                for (int bt = 0; bt < 2; bt++) {
                    const int row = wn * 32 + bt * 16 + lrow;
                    uint32_t r0, r1, r2, r3;
                    ldsm_x4(r0, r1, r2, r3, b_l + swz64(row * 64 + kb));
                    blf[bt * 2 + 0][0] = r0; blf[bt * 2 + 1][0] = r1;
                    blf[bt * 2 + 0][1] = r2; blf[bt * 2 + 1][1] = r3;
                }
#pragma unroll
                for (int mt = 0; mt < 4; mt++)
#pragma unroll
                    for (int nt = 0; nt < 4; nt++)
                        mma_f16(acc[mt][nt], ahf[mt], blf[nt]);
            }
            // --- Bh fragments (reused for 2 products), product Ah*Bh ---
            uint32_t bhf[4][2];
#pragma unroll
            for (int bt = 0; bt < 2; bt++) {
                const int row = wn * 32 + bt * 16 + lrow;
                uint32_t r0, r1, r2, r3;
                ldsm_x4(r0, r1, r2, r3, b_h + swz64(row * 64 + kb));
                bhf[bt * 2 + 0][0] = r0; bhf[bt * 2 + 1][0] = r1;
                bhf[bt * 2 + 0][1] = r2; bhf[bt * 2 + 1][1] = r3;
            }
#pragma unroll
            for (int mt = 0; mt < 4; mt++)
#pragma unroll
                for (int nt = 0; nt < 4; nt++)
                    mma_f16(acc[mt][nt], ahf[mt], bhf[nt]);

            // --- Al fragments, product Al*Bh ---
#pragma unroll
            for (int mt = 0; mt < 4; mt++) {
                const int row = wm * 64 + mt * 16 + lrow;
                uint32_t alf[4];
                ldsm_x4(alf[0], alf[1], alf[2], alf[3],
                        a_l + swz64(row * 64 + kb));
#pragma unroll
                for (int nt = 0; nt < 4; nt++)
                    mma_f16(acc[mt][nt], alf, bhf[nt]);
            }
        }
    }

    // ---- epilogue: bias + permuted store into scan layout ----
    const int g = lane >> 2, t4 = lane & 3;
#pragma unroll
    for (int mt = 0; mt < 4; mt++) {
#pragma unroll
        for (int nt = 0; nt < 4; nt++) {
            const int rm = by * 128 + wm * 64 + mt * 16 + g;
            const int cg = bx * 128 + wn * 32 + nt * 8 + t4 * 2;
            const float b0 = __ldg(&bias[cg]);
            const float b1 = __ldg(&bias[cg + 1]);
            const int nh = cg >> 8, ij = cg & 255;
            const int b_ = rm >> 11, t_ = rm & (TLEN - 1);
            float* o = C + (((size_t)(b_ * 16 + nh) * TLEN + t_) * 256 + ij);
            *(float2*)o = make_float2(acc[mt][nt][0] + b0, acc[mt][nt][1] + b1);
            *(float2*)(o + 8 * 256) = make_float2(acc[mt][nt][2] + b0, acc[mt][nt][3] + b1);
        }
    }
}

// ---------------------------------------------------------------------------
// Pass-based HMMA GEMM (kept for GEMM2): D = Ah*Bl + Al*Bh + Ah*Bh (+bias,gelu)
// ---------------------------------------------------------------------------
#define STAGE_BYTES 32768            // A 16KB + B 16KB
#define GEMM_SMEM   (1024 + 3 * STAGE_BYTES)

template <bool GELU, int KDIM, int NDIM>
__global__ __launch_bounds__(256, 2)
void gemm_mma_kernel(const __half* __restrict__ Ah, const __half* __restrict__ Al,
                     const __half* __restrict__ Bh, const __half* __restrict__ Bl,
                     const float* __restrict__ bias, float* __restrict__ C)
{
    constexpr int CHUNKS = KDIM / 64;
    constexpr int NITER  = 3 * CHUNKS;

    extern __shared__ char smem[];
    const uint32_t tiles = (smem_u32(smem) + 1023u) & ~1023u;
    const int tid = threadIdx.x;
    const int lane = tid & 31, warp = tid >> 5;
    const int wm = warp & 1, wn = warp >> 1;
    const int bx = blockIdx.x;
    const int by = blockIdx.y;

    const __half* Asrc[3] = {Ah, Al, Ah};
    const __half* Bsrc[3] = {Bl, Bh, Bh};

    const int lr = tid >> 3;
    const int lc = (tid & 7) * 16;

    auto issue_loads = [&](int iter) {
        const int pass = iter / CHUNKS, chunk = iter % CHUNKS, stage = iter % 3;
        const uint32_t a_s = tiles + stage * STAGE_BYTES;
        const uint32_t b_s = a_s + 16384;
        const __half* Ap = Asrc[pass] + (size_t)(by * 128) * KDIM + chunk * 64 + (lc >> 1);
        const __half* Bp = Bsrc[pass] + (size_t)(bx * 128) * KDIM + chunk * 64 + (lc >> 1);
#pragma unroll
        for (int it = 0; it < 4; it++) {
            const int row = it * 32 + lr;
            CP_ASYNC16(a_s + swz(row * 128 + lc), Ap + (size_t)row * KDIM);
        }
#pragma unroll
        for (int it = 0; it < 4; it++) {
            const int row = it * 32 + lr;
            CP_ASYNC16(b_s + swz(row * 128 + lc), Bp + (size_t)row * KDIM);
        }
    };

    float acc[4][4][4];
#pragma unroll
    for (int i = 0; i < 4; i++)
#pragma unroll
        for (int j = 0; j < 4; j++)
#pragma unroll
            for (int k = 0; k < 4; k++) acc[i][j][k] = 0.0f;

    const int lrow = lane & 15;
    const int lkof = (lane >> 4) * 16;

    for (int j = 0; j < 2; j++) { issue_loads(j); CP_COMMIT(); }

    for (int i = 0; i < NITER; i++) {
        CP_WAIT1();
        __syncthreads();
        if (i + 2 < NITER) issue_loads(i + 2);
        CP_COMMIT();

        const uint32_t a_s = tiles + (i % 3) * STAGE_BYTES;
        const uint32_t b_s = a_s + 16384;

#pragma unroll
        for (int ks = 0; ks < 4; ks++) {
            const int kb = ks * 32 + lkof;
            uint32_t a[4][4], b[4][2];
#pragma unroll
            for (int mt = 0; mt < 4; mt++) {
                const int row = wm * 64 + mt * 16 + lrow;
                ldsm_x4(a[mt][0], a[mt][1], a[mt][2], a[mt][3],
                        a_s + swz(row * 128 + kb));
            }
#pragma unroll
            for (int bt = 0; bt < 2; bt++) {
                const int row = wn * 32 + bt * 16 + lrow;
                uint32_t r0, r1, r2, r3;
                ldsm_x4(r0, r1, r2, r3, b_s + swz(row * 128 + kb));
                b[bt * 2 + 0][0] = r0; b[bt * 2 + 1][0] = r1;
                b[bt * 2 + 0][1] = r2; b[bt * 2 + 1][1] = r3;
            }
#pragma unroll
            for (int mt = 0; mt < 4; mt++)
#pragma unroll
                for (int nt = 0; nt < 4; nt++)
                    mma_f16(acc[mt][nt], a[mt], b[nt]);
        }
    }

    const int g = lane >> 2, t4 = lane & 3;
#pragma unroll
    for (int mt = 0; mt < 4; mt++) {
#pragma unroll
        for (int nt = 0; nt < 4; nt++) {
            const int rm = by * 128 + wm * 64 + mt * 16 + g;
            const int cg = bx * 128 + wn * 32 + nt * 8 + t4 * 2;
            const float b0 = __ldg(&bias[cg]);
            const float b1 = __ldg(&bias[cg + 1]);
            float v0 = acc[mt][nt][0] + b0;
            float v1 = acc[mt][nt][1] + b1;
            float v2 = acc[mt][nt][2] + b0;
            float v3 = acc[mt][nt][3] + b1;
            if (GELU) {
                v0 = 0.5f * v0 * (1.0f + erff(v0 * 0.70710678118654752f));
                v1 = 0.5f * v1 * (1.0f + erff(v1 * 0.70710678118654752f));
                v2 = 0.5f * v2 * (1.0f + erff(v2 * 0.70710678118654752f));
                v3 = 0.5f * v3 * (1.0f + erff(v3 * 0.70710678118654752f));
            }
            float* o = C + ((size_t)rm * NDIM + cg);
            *(float2*)o = make_float2(v0, v1);
            *(float2*)(o + (size_t)8 * NDIM) = make_float2(v2, v3);
        }
    }
}

// ---------------------------------------------------------------------------
// Sequential scan on UNNORMALIZED matrices (scale-invariant), deep register
// prefetch (ring of 8, MLP=8), deferred vector normalization (rescale /4).
// ---------------------------------------------------------------------------
#define PF 8

__global__ __launch_bounds__(32)
void scan_kernel(const float* __restrict__ mn, __half* __restrict__ xh,
                 __half* __restrict__ xl)
{
    const unsigned F = 0xffffffffu;
    const int lane = threadIdx.x & 31;
    const int s = blockIdx.x & 127;
    const int d = blockIdx.x >> 7;
    const int b = s >> 4;
    const int nh = s & 15;

    const int laneoff = (lane & 15) * 16 + (lane >> 4) * 8;
    const float* base = mn + (size_t)s * (TLEN * 256) + laneoff;
    const int h8 = (lane >> 4) << 3;

    const int t0 = d ? (TLEN - 1) : 0;
    const int dt = d ? -1 : 1;

    float u = ((lane & 15) == 0) ? 1.0f : 0.0f;
    const size_t xoff = (size_t)b * TLEN * 512 + nh * 32 + d * 16 + (lane & 15);

    float4 r0[PF], r1[PF];
#pragma unroll
    for (int j = 0; j < PF; j++) {
        const int tj = t0 + j * dt;
        const float* q = base + (size_t)tj * 256;
        r0[j] = __ldg((const float4*)q);
        r1[j] = __ldg((const float4*)(q + 4));
    }

#pragma unroll 1
    for (int blk = 0; blk < TLEN / PF; ++blk) {
#pragma unroll
        for (int sub = 0; sub < PF; ++sub) {
            const int step = blk * PF + sub;
            const int t = t0 + step * dt;

            const float4 c0 = r0[sub];
            const float4 c1 = r1[sub];

            int tp = t + PF * dt;
            tp = tp < 0 ? 0 : (tp > TLEN - 1 ? TLEN - 1 : tp);
            const float* q = base + (size_t)tp * 256;
            r0[sub] = __ldg((const float4*)q);
            r1[sub] = __ldg((const float4*)(q + 4));

            const float vb0 = __shfl_sync(F, u, h8 + 0);
            const float vb1 = __shfl_sync(F, u, h8 + 1);
            const float vb2 = __shfl_sync(F, u, h8 + 2);
            const float vb3 = __shfl_sync(F, u, h8 + 3);
            const float vb4 = __shfl_sync(F, u, h8 + 4);
            const float vb5 = __shfl_sync(F, u, h8 + 5);
            const float vb6 = __shfl_sync(F, u, h8 + 6);
            const float vb7 = __shfl_sync(F, u, h8 + 7);

            float pA = c0.x * vb0;
            pA = fmaf(c0.y, vb1, pA);
            pA = fmaf(c0.z, vb2, pA);
            pA = fmaf(c0.w, vb3, pA);
            float pB = c1.x * vb4;
            pB = fmaf(c1.y, vb5, pB);
            pB = fmaf(c1.z, vb6, pB);
            pB = fmaf(c1.w, vb7, pB);
            const float pp = pA + pB;

            const float nv = pp + __shfl_xor_sync(F, pp, 16);

            float ss = nv * nv;
            ss += __shfl_xor_sync(F, ss, 8);
            ss += __shfl_xor_sync(F, ss, 4);
            ss += __shfl_xor_sync(F, ss, 2);
            ss += __shfl_xor_sync(F, ss, 1);
            const float w = nv / (sqrtf(ss) + 1e-6f);

            if (lane < 16) {
                __half h, l;
                split_f16(w, h, l);
                xh[xoff + (size_t)t * 512] = h;
                xl[xoff + (size_t)t * 512] = l;
            }

            u = ((sub & 3) == 3) ? w : nv;
        }
    }
}

// ---------------------------------------------------------------------------
// Launch
// ---------------------------------------------------------------------------
extern "C" void kernel_launch(void* const* d_in, const int* in_sizes, int n_in,
                              void* d_out, int out_size)
{
    const float* hs = (const float*)d_in[0];
    const float* Wm = (const float*)d_in[1];
    const float* bm = (const float*)d_in[2];
    const float* Wo = (const float*)d_in[3];
    const float* bo = (const float*)d_in[4];
    float* out = (float*)d_out;

    float* pm;
    __half *pah, *pal, *pbh, *pbl, *pxh, *pxl, *pwh, *pwl;
    cudaGetSymbolAddress((void**)&pm, g_m);
    cudaGetSymbolAddress((void**)&pah, g_ah);
    cudaGetSymbolAddress((void**)&pal, g_al);
    cudaGetSymbolAddress((void**)&pbh, g_bh);
    cudaGetSymbolAddress((void**)&pbl, g_bl);
    cudaGetSymbolAddress((void**)&pxh, g_xh);
    cudaGetSymbolAddress((void**)&pxl, g_xl);
    cudaGetSymbolAddress((void**)&pwh, g_wh);
    cudaGetSymbolAddress((void**)&pwl, g_wl);

    // 0) fp16 splits
    convA_kernel<<<(BT * HIDD / 4) / 256, 256>>>(hs, pah, pal);
    convW_kernel<<<dim3(N1 / 32, HIDD / 32), dim3(32, 32)>>>(Wm, pbh, pbl, HIDD, N1);
    convW_kernel<<<dim3(HIDD / 32, K2D / 32), dim3(32, 32)>>>(Wo, pwh, pwl, K2D, HIDD);

    // 1) GEMM1 fused-chunk (HMMA fp16 split, frag reuse) -> scan layout (+bias)
    cudaFuncSetAttribute(gemm1_fused_kernel,
                         cudaFuncAttributeMaxDynamicSharedMemorySize, G1_SMEM);
    gemm1_fused_kernel<<<dim3(N1 / 128, BT / 128), 256, G1_SMEM>>>(
        pah, pal, pbh, pbl, bm, pm);

    // 2) Bidirectional scan (scale-invariant; no fro-norm) -> fp16 hi/lo
    scan_kernel<<<256, 32>>>(pm, pxh, pxl);

    // 3) GEMM2 (pass-based HMMA): out = gelu(x @ W_out + b_out)
    cudaFuncSetAttribute(gemm_mma_kernel<true, K2D, HIDD>,
                         cudaFuncAttributeMaxDynamicSharedMemorySize, GEMM_SMEM);
    gemm_mma_kernel<true, K2D, HIDD>
        <<<dim3(HIDD / 128, BT / 128), 256, GEMM_SMEM>>>(pxh, pxl, pwh, pwl, bo, out);
}

// round 13
// speedup vs baseline: 2.5065x; 1.0024x over previous
#include <cuda_runtime.h>
#include <cuda_fp16.h>
#include <cstdint>
#include <math.h>

// Problem constants
#define BB     8
#define TLEN   2048
#define HIDD   1024
#define NHH    16
#define MDD    16
#define BT     (BB * TLEN)          // 16384 rows
#define N1     (NHH * MDD * MDD)    // 4096
#define K2D    (NHH * MDD * 2)      // 512

// ---------------------------------------------------------------------------
// Scratch (device globals — no allocation allowed)
// ---------------------------------------------------------------------------
__device__ float  g_m[(size_t)BT * N1];               // scan layout [s][t][256] (UNNORMALIZED)
__device__ __half g_ah[(size_t)BT * HIDD];            // hs hi
__device__ __half g_al[(size_t)BT * HIDD];            // hs lo (unscaled)
__device__ __half g_bh[(size_t)N1 * HIDD];            // W_mat^T hi  [n][k]
__device__ __half g_bl[(size_t)N1 * HIDD];            // W_mat^T lo  [n][k]
__device__ __half g_xh[(size_t)BT * K2D];             // scan out hi
__device__ __half g_xl[(size_t)BT * K2D];             // scan out lo
__device__ __half g_wh[(size_t)HIDD * K2D];           // W_out^T hi [n][k]
__device__ __half g_wl[(size_t)HIDD * K2D];           // W_out^T lo [n][k]

// ---------------------------------------------------------------------------
// Helpers
// ---------------------------------------------------------------------------
__device__ __forceinline__ uint32_t smem_u32(const void* p) {
    uint32_t a;
    asm("{ .reg .u64 t; cvta.to.shared.u64 t, %1; cvt.u32.u64 %0, t; }" : "=r"(a) : "l"(p));
    return a;
}
#define CP_ASYNC16(dst, src) \
    asm volatile("cp.async.cg.shared.global [%0], [%1], 16;\n" :: "r"(dst), "l"(src) : "memory")
#define CP_COMMIT()  asm volatile("cp.async.commit_group;\n" ::: "memory")
#define CP_WAIT1()   asm volatile("cp.async.wait_group 1;\n" ::: "memory")

__device__ __forceinline__ void ldsm_x4(uint32_t& r0, uint32_t& r1, uint32_t& r2,
                                        uint32_t& r3, uint32_t addr) {
    asm volatile("ldmatrix.sync.aligned.m8n8.x4.shared.b16 {%0,%1,%2,%3}, [%4];"
                 : "=r"(r0), "=r"(r1), "=r"(r2), "=r"(r3) : "r"(addr));
}
__device__ __forceinline__ void mma_f16(float* c, const uint32_t* a, const uint32_t* b) {
    asm volatile(
        "mma.sync.aligned.m16n8k16.row.col.f32.f16.f16.f32 "
        "{%0,%1,%2,%3}, {%4,%5,%6,%7}, {%8,%9}, {%0,%1,%2,%3};"
        : "+f"(c[0]), "+f"(c[1]), "+f"(c[2]), "+f"(c[3])
        : "r"(a[0]), "r"(a[1]), "r"(a[2]), "r"(a[3]), "r"(b[0]), "r"(b[1]));
}
__device__ __forceinline__ uint32_t swz64(uint32_t off) { return off ^ ((off >> 3) & 0x30); } // SW64

__device__ __forceinline__ void split_f16(float a, __half& h, __half& l) {
    h = __float2half_rn(a);
    l = __float2half_rn(a - __half2float(h));
}

// ---------------------------------------------------------------------------
// Conversion kernels
// ---------------------------------------------------------------------------
struct alignas(8) h4 { __half v[4]; };

__global__ __launch_bounds__(256)
void convA_kernel(const float* __restrict__ x, __half* __restrict__ hi,
                  __half* __restrict__ lo)
{
    const int i = blockIdx.x * blockDim.x + threadIdx.x;
    float4 v = ((const float4*)x)[i];
    h4 h, l;
    float a[4] = {v.x, v.y, v.z, v.w};
#pragma unroll
    for (int j = 0; j < 4; j++) split_f16(a[j], h.v[j], l.v[j]);
    ((h4*)hi)[i] = h;
    ((h4*)lo)[i] = l;
}

// Transpose W (KR x NC, row-major) -> [n][k] fp16 hi/lo
__global__ __launch_bounds__(1024)
void convW_kernel(const float* __restrict__ W, __half* __restrict__ wh,
                  __half* __restrict__ wl, int KR, int NC)
{
    __shared__ float tile[32][33];
    const int n_in = blockIdx.x * 32 + threadIdx.x;
    const int k_in = blockIdx.y * 32 + threadIdx.y;
    tile[threadIdx.y][threadIdx.x] = W[(size_t)k_in * NC + n_in];
    __syncthreads();
    const int n_out = blockIdx.x * 32 + threadIdx.y;
    const int k_out = blockIdx.y * 32 + threadIdx.x;
    const float v = tile[threadIdx.x][threadIdx.y];
    __half h, l;
    split_f16(v, h, l);
    const size_t o = (size_t)n_out * KR + k_out;
    wh[o] = h;
    wl[o] = l;
}

// ---------------------------------------------------------------------------
// FUSED-CHUNK HMMA GEMM, fp16 2-term split, single fp32 accumulator:
//   D = Ah*Bl + Al*Bh + Ah*Bh   [+ bias]
// Per K-chunk (32 halfs) the 4 tiles (Ah,Al,Bh,Bl) are loaded once; per ks
// B fragments are loaded once (16 regs) and per-mt the two A fragments feed
// 12 MMAs (small products first) — peak fragment liveness 24 regs, giving
// ptxas room to software-pipeline the LDSM->MMA dependency.
// CTA 128x128, 8 warps (2m x 4n), SW64 swizzle, 3-stage ring, 2 CTAs/SM.
// ---------------------------------------------------------------------------
#define CH_K     32                         // halfs per chunk
#define TILE_B   8192                       // 128 rows * 64 bytes
#define ST_B     (4 * TILE_B)               // 32KB per stage (Ah,Al,Bh,Bl)
#define G_SMEM   (1024 + 3 * ST_B)

template <bool PERM, bool GELU, int KDIM, int NDIM>
__global__ __launch_bounds__(256, 2)
void gemm_fused_kernel(const __half* __restrict__ Ah, const __half* __restrict__ Al,
                       const __half* __restrict__ Bh, const __half* __restrict__ Bl,
                       const float* __restrict__ bias, float* __restrict__ C)
{
    constexpr int NCHUNK = KDIM / CH_K;

    extern __shared__ char smem[];
    const uint32_t tiles = (smem_u32(smem) + 1023u) & ~1023u;
    const int tid = threadIdx.x;
    const int lane = tid & 31, warp = tid >> 5;
    const int wm = warp & 1, wn = warp >> 1;     // 2 x 4 warp grid
    const int bx = blockIdx.x;                   // N tile
    const int by = blockIdx.y;                   // M tile

    const int lr  = tid >> 2;          // 0..63 (row)
    const int lcb = (tid & 3) * 16;    // byte col within 64B row

    const __half* Asrcs[2] = {Ah, Al};
    const __half* Bsrcs[2] = {Bh, Bl};

    auto issue_loads = [&](int chunk) {
        const int stage = chunk % 3;
        const uint32_t s = tiles + stage * ST_B;
        const int koff = chunk * CH_K + (lcb >> 1);
#pragma unroll
        for (int a = 0; a < 2; a++) {
            const __half* Ap = Asrcs[a] + (size_t)(by * 128 + lr) * KDIM + koff;
            const uint32_t d = s + a * TILE_B;
            CP_ASYNC16(d + swz64(lr * 64 + lcb), Ap);
            CP_ASYNC16(d + swz64((lr + 64) * 64 + lcb), Ap + (size_t)64 * KDIM);
        }
#pragma unroll
        for (int b = 0; b < 2; b++) {
            const __half* Bp = Bsrcs[b] + (size_t)(bx * 128 + lr) * KDIM + koff;
            const uint32_t d = s + (2 + b) * TILE_B;
            CP_ASYNC16(d + swz64(lr * 64 + lcb), Bp);
            CP_ASYNC16(d + swz64((lr + 64) * 64 + lcb), Bp + (size_t)64 * KDIM);
        }
    };

    float acc[4][4][4];
#pragma unroll
    for (int i = 0; i < 4; i++)
#pragma unroll
        for (int j = 0; j < 4; j++)
#pragma unroll
            for (int k = 0; k < 4; k++) acc[i][j][k] = 0.0f;

    const int lrow = lane & 15;
    const int lkof = (lane >> 4) * 16;

    issue_loads(0); CP_COMMIT();
    issue_loads(1); CP_COMMIT();

    for (int i = 0; i < NCHUNK; i++) {
        CP_WAIT1();
        __syncthreads();
        if (i + 2 < NCHUNK) issue_loads(i + 2);
        CP_COMMIT();

        const uint32_t s   = tiles + (i % 3) * ST_B;
        const uint32_t a_h = s;
        const uint32_t a_l = s + TILE_B;
        const uint32_t b_h = s + 2 * TILE_B;
        const uint32_t b_l = s + 3 * TILE_B;

#pragma unroll
        for (int ks = 0; ks < 2; ks++) {
            const int kb = ks * 32 + lkof;      // byte col

            // B fragments once per ks (16 regs live)
            uint32_t bhf[4][2], blf[4][2];
#pragma unroll
            for (int bt = 0; bt < 2; bt++) {
                const int row = wn * 32 + bt * 16 + lrow;
                uint32_t r0, r1, r2, r3;
                ldsm_x4(r0, r1, r2, r3, b_l + swz64(row * 64 + kb));
                blf[bt * 2 + 0][0] = r0; blf[bt * 2 + 1][0] = r1;
                blf[bt * 2 + 0][1] = r2; blf[bt * 2 + 1][1] = r3;
                ldsm_x4(r0, r1, r2, r3, b_h + swz64(row * 64 + kb));
                bhf[bt * 2 + 0][0] = r0; bhf[bt * 2 + 1][0] = r1;
                bhf[bt * 2 + 0][1] = r2; bhf[bt * 2 + 1][1] = r3;
            }

            // per-mt: 2 LDSM feed 12 MMAs (small products first)
#pragma unroll
            for (int mt = 0; mt < 4; mt++) {
                const int row = wm * 64 + mt * 16 + lrow;
                uint32_t ahf[4], alf[4];
                ldsm_x4(ahf[0], ahf[1], ahf[2], ahf[3],
                        a_h + swz64(row * 64 + kb));
                ldsm_x4(alf[0], alf[1], alf[2], alf[3],
                        a_l + swz64(row * 64 + kb));
#pragma unroll
                for (int nt = 0; nt < 4; nt++)
                    mma_f16(acc[mt][nt], ahf, blf[nt]);
#pragma unroll
                for (int nt = 0; nt < 4; nt++)
                    mma_f16(acc[mt][nt], alf, bhf[nt]);
#pragma unroll
                for (int nt = 0; nt < 4; nt++)
                    mma_f16(acc[mt][nt], ahf, bhf[nt]);
            }
        }
    }

    // ---- epilogue ----
    const int g = lane >> 2, t4 = lane & 3;
#pragma unroll
    for (int mt = 0; mt < 4; mt++) {
#pragma unroll
        for (int nt = 0; nt < 4; nt++) {
            const int rm = by * 128 + wm * 64 + mt * 16 + g;
            const int cg = bx * 128 + wn * 32 + nt * 8 + t4 * 2;
            const float b0 = __ldg(&bias[cg]);
            const float b1 = __ldg(&bias[cg + 1]);
            float v0 = acc[mt][nt][0] + b0;
            float v1 = acc[mt][nt][1] + b1;
            float v2 = acc[mt][nt][2] + b0;
            float v3 = acc[mt][nt][3] + b1;
            if (GELU) {
                v0 = 0.5f * v0 * (1.0f + erff(v0 * 0.70710678118654752f));
                v1 = 0.5f * v1 * (1.0f + erff(v1 * 0.70710678118654752f));
                v2 = 0.5f * v2 * (1.0f + erff(v2 * 0.70710678118654752f));
                v3 = 0.5f * v3 * (1.0f + erff(v3 * 0.70710678118654752f));
            }
            if (PERM) {
                const int nh = cg >> 8, ij = cg & 255;
                const int b_ = rm >> 11, t_ = rm & (TLEN - 1);
                float* o = C + (((size_t)(b_ * 16 + nh) * TLEN + t_) * 256 + ij);
                *(float2*)o = make_float2(v0, v1);
                *(float2*)(o + 8 * 256) = make_float2(v2, v3);
            } else {
                float* o = C + ((size_t)rm * NDIM + cg);
                *(float2*)o = make_float2(v0, v1);
                *(float2*)(o + (size_t)8 * NDIM) = make_float2(v2, v3);
            }
        }
    }
}

// ---------------------------------------------------------------------------
// Sequential scan on UNNORMALIZED matrices (scale-invariant), deep register
// prefetch (ring of 8, MLP=8), deferred vector normalization (rescale /4).
// ---------------------------------------------------------------------------
#define PF 8

__global__ __launch_bounds__(32)
void scan_kernel(const float* __restrict__ mn, __half* __restrict__ xh,
                 __half* __restrict__ xl)
{
    const unsigned F = 0xffffffffu;
    const int lane = threadIdx.x & 31;
    const int s = blockIdx.x & 127;
    const int d = blockIdx.x >> 7;
    const int b = s >> 4;
    const int nh = s & 15;

    const int laneoff = (lane & 15) * 16 + (lane >> 4) * 8;
    const float* base = mn + (size_t)s * (TLEN * 256) + laneoff;
    const int h8 = (lane >> 4) << 3;

    const int t0 = d ? (TLEN - 1) : 0;
    const int dt = d ? -1 : 1;

    float u = ((lane & 15) == 0) ? 1.0f : 0.0f;
    const size_t xoff = (size_t)b * TLEN * 512 + nh * 32 + d * 16 + (lane & 15);

    float4 r0[PF], r1[PF];
#pragma unroll
    for (int j = 0; j < PF; j++) {
        const int tj = t0 + j * dt;
        const float* q = base + (size_t)tj * 256;
        r0[j] = __ldg((const float4*)q);
        r1[j] = __ldg((const float4*)(q + 4));
    }

#pragma unroll 1
    for (int blk = 0; blk < TLEN / PF; ++blk) {
#pragma unroll
        for (int sub = 0; sub < PF; ++sub) {
            const int step = blk * PF + sub;
            const int t = t0 + step * dt;

            const float4 c0 = r0[sub];
            const float4 c1 = r1[sub];

            int tp = t + PF * dt;
            tp = tp < 0 ? 0 : (tp > TLEN - 1 ? TLEN - 1 : tp);
            const float* q = base + (size_t)tp * 256;
            r0[sub] = __ldg((const float4*)q);
            r1[sub] = __ldg((const float4*)(q + 4));

            const float vb0 = __shfl_sync(F, u, h8 + 0);
            const float vb1 = __shfl_sync(F, u, h8 + 1);
            const float vb2 = __shfl_sync(F, u, h8 + 2);
            const float vb3 = __shfl_sync(F, u, h8 + 3);
            const float vb4 = __shfl_sync(F, u, h8 + 4);
            const float vb5 = __shfl_sync(F, u, h8 + 5);
            const float vb6 = __shfl_sync(F, u, h8 + 6);
            const float vb7 = __shfl_sync(F, u, h8 + 7);

            float pA = c0.x * vb0;
            pA = fmaf(c0.y, vb1, pA);
            pA = fmaf(c0.z, vb2, pA);
            pA = fmaf(c0.w, vb3, pA);
            float pB = c1.x * vb4;
            pB = fmaf(c1.y, vb5, pB);
            pB = fmaf(c1.z, vb6, pB);
            pB = fmaf(c1.w, vb7, pB);
            const float pp = pA + pB;

            const float nv = pp + __shfl_xor_sync(F, pp, 16);

            float ss = nv * nv;
            ss += __shfl_xor_sync(F, ss, 8);
            ss += __shfl_xor_sync(F, ss, 4);
            ss += __shfl_xor_sync(F, ss, 2);
            ss += __shfl_xor_sync(F, ss, 1);
            const float w = nv / (sqrtf(ss) + 1e-6f);

            if (lane < 16) {
                __half h, l;
                split_f16(w, h, l);
                xh[xoff + (size_t)t * 512] = h;
                xl[xoff + (size_t)t * 512] = l;
            }

            u = ((sub & 3) == 3) ? w : nv;
        }
    }
}

// ---------------------------------------------------------------------------
// Launch
// ---------------------------------------------------------------------------
extern "C" void kernel_launch(void* const* d_in, const int* in_sizes, int n_in,
                              void* d_out, int out_size)
{
    const float* hs = (const float*)d_in[0];
    const float* Wm = (const float*)d_in[1];
    const float* bm = (const float*)d_in[2];
    const float* Wo = (const float*)d_in[3];
    const float* bo = (const float*)d_in[4];
    float* out = (float*)d_out;

    float* pm;
    __half *pah, *pal, *pbh, *pbl, *pxh, *pxl, *pwh, *pwl;
    cudaGetSymbolAddress((void**)&pm, g_m);
    cudaGetSymbolAddress((void**)&pah, g_ah);
    cudaGetSymbolAddress((void**)&pal, g_al);
    cudaGetSymbolAddress((void**)&pbh, g_bh);
    cudaGetSymbolAddress((void**)&pbl, g_bl);
    cudaGetSymbolAddress((void**)&pxh, g_xh);
    cudaGetSymbolAddress((void**)&pxl, g_xl);
    cudaGetSymbolAddress((void**)&pwh, g_wh);
    cudaGetSymbolAddress((void**)&pwl, g_wl);

    // 0) fp16 splits
    convA_kernel<<<(BT * HIDD / 4) / 256, 256>>>(hs, pah, pal);
    convW_kernel<<<dim3(N1 / 32, HIDD / 32), dim3(32, 32)>>>(Wm, pbh, pbl, HIDD, N1);
    convW_kernel<<<dim3(HIDD / 32, K2D / 32), dim3(32, 32)>>>(Wo, pwh, pwl, K2D, HIDD);

    // 1) GEMM1 fused-chunk -> scan layout (+bias), unnormalized
    cudaFuncSetAttribute(gemm_fused_kernel<true, false, HIDD, N1>,
                         cudaFuncAttributeMaxDynamicSharedMemorySize, G_SMEM);
    gemm_fused_kernel<true, false, HIDD, N1>
        <<<dim3(N1 / 128, BT / 128), 256, G_SMEM>>>(pah, pal, pbh, pbl, bm, pm);

    // 2) Bidirectional scan (scale-invariant; no fro-norm) -> fp16 hi/lo
    scan_kernel<<<256, 32>>>(pm, pxh, pxl);

    // 3) GEMM2 fused-chunk: out = gelu(x @ W_out + b_out)
    cudaFuncSetAttribute(gemm_fused_kernel<false, true, K2D, HIDD>,
                         cudaFuncAttributeMaxDynamicSharedMemorySize, G_SMEM);
    gemm_fused_kernel<false, true, K2D, HIDD>
        <<<dim3(HIDD / 128, BT / 128), 256, G_SMEM>>>(pxh, pxl, pwh, pwl, bo, out);
}